// round 2
// baseline (speedup 1.0000x reference)
#include <cuda_runtime.h>
#include <math.h>

// Problem constants
#define Bq 4
#define CCn 21
#define Hh 96
#define Ww 96
#define Nn (Hh*Ww)          // 9216
#define EH (Hh*(Ww-1))      // 9120
#define EV ((Hh-1)*Ww)      // 9120
#define Ee (EH+EV)          // 18240
#define CL 3
#define CHh 512

// ---- device scratch (static, no allocation) ----
__device__ float g_prob[Bq*CCn*Nn];
__device__ float g_wE[2][Bq][Ee];
__device__ int   g_parent[2][Bq][Nn];
__device__ int   g_order[2][Bq][Nn];
__device__ int   g_levelStart[2][Bq][Nn+2];
__device__ int   g_nLevels[2][Bq];
__device__ float g_wnode[2][Bq][Nn];
__device__ float g_F1[Bq*22*Nn];
__device__ float g_F2[Bq*22*Nn];
__device__ double g_acc[2];

__device__ __forceinline__ void edge_ep(int e, int& a, int& b) {
    if (e < EH) { int r = e / (Ww-1); int c = e - r*(Ww-1); a = r*Ww + c; b = a + 1; }
    else        { int e2 = e - EH;    a = e2;               b = e2 + Ww; }
}

// ---------------- K1: sigmoid + zero accumulators ----------------
__global__ void k_prep(const float* __restrict__ preds) {
    int i = blockIdx.x*blockDim.x + threadIdx.x;
    if (blockIdx.x == 0 && threadIdx.x == 0) { g_acc[0] = 0.0; g_acc[1] = 0.0; }
    if (i < Bq*CCn*Nn) g_prob[i] = 1.0f/(1.0f + expf(-preds[i]));
}

// ---------------- K2: edge weights (double accumulation) ----------------
__global__ void k_edgew(const float* __restrict__ low, const float* __restrict__ high) {
    int e = blockIdx.x*blockDim.x + threadIdx.x;
    int t = blockIdx.y, b = blockIdx.z;
    if (e >= Ee) return;
    int a, bn; edge_ep(e, a, bn);
    const float* f = t ? (high + (size_t)b*CHh*Nn) : (low + (size_t)b*CL*Nn);
    int C = t ? CHh : CL;
    double acc = 0.0;
    for (int c = 0; c < C; c++) {
        double d = (double)f[(size_t)c*Nn + a] - (double)f[(size_t)c*Nn + bn];
        acc += d*d;
    }
    g_wE[t][b][e] = (float)acc;
}

// ---------------- K3: Boruvka MST + CSR + BFS (one block per (t,b)) ----------------
// shared layout (bytes):
//  flag     [0,      18240)  uchar[Ee]          (persists both phases)
//  phase1:  wsh  [18240,91200) float[Ee]
//           best [91200,164928) u64[Nn]
//           comp [164928,201792) int[Nn]
//  phase2:  rowStart [18240,55108)  int[Nn+1]
//           adjList  [55108,128828) int[2*(Nn-1)]
//           depth    [128828,165692) int[Nn]   (also cursor / scan temp)
//           orderS   [165692,202556) int[Nn]
#define MST_SMEM 202560

__global__ void __launch_bounds__(1024,1) k_mst_bfs() {
    extern __shared__ unsigned char smem[];
    const int t = blockIdx.x >> 2, b = blockIdx.x & 3;
    const int tid = threadIdx.x, NT = blockDim.x;

    unsigned char* flag = smem;
    float* wsh = (float*)(smem + 18240);
    unsigned long long* best = (unsigned long long*)(smem + 91200);
    int* comp = (int*)(smem + 164928);
    __shared__ int s_merged, s_changed, s_head;

    for (int e = tid; e < Ee; e += NT) { wsh[e] = g_wE[t][b][e]; flag[e] = 0; }
    for (int i = tid; i < Nn; i += NT) comp[i] = i;
    __syncthreads();

    // ---- Boruvka rounds ----
    for (int round = 0; round < 20; round++) {
        for (int i = tid; i < Nn; i += NT) best[i] = 0xFFFFFFFFFFFFFFFFULL;
        if (tid == 0) s_merged = 0;
        __syncthreads();
        for (int e = tid; e < Ee; e += NT) {
            int a, bn; edge_ep(e, a, bn);
            int ca = comp[a], cb = comp[bn];
            if (ca != cb) {
                unsigned long long key =
                    ((unsigned long long)__float_as_uint(wsh[e]) << 32) | (unsigned)e;
                atomicMin(&best[ca], key);
                atomicMin(&best[cb], key);
            }
        }
        __syncthreads();
        // hooking: phase A (read-only decide) then phase B (write)
        int myRoot[9], myOther[9], myEdge[9]; int nMy = 0;
        for (int i = tid; i < Nn; i += NT) {
            if (comp[i] == i && best[i] != 0xFFFFFFFFFFFFFFFFULL) {
                unsigned long long k = best[i];
                int e = (int)(k & 0xFFFFFFFFu);
                int a, bn; edge_ep(e, a, bn);
                int ca = comp[a], cb = comp[bn];
                int other = (ca == i) ? cb : ca;
                bool mutual = (best[other] == k);
                if (!mutual || other < i) {
                    myRoot[nMy] = i; myOther[nMy] = other; myEdge[nMy] = e; nMy++;
                }
            }
        }
        __syncthreads();
        for (int j = 0; j < nMy; j++) { comp[myRoot[j]] = myOther[j]; flag[myEdge[j]] = 1; }
        if (nMy) s_merged = 1;
        __syncthreads();
        int m = s_merged;
        __syncthreads();
        if (!m) break;
        // pointer jumping to full compression
        for (;;) {
            if (tid == 0) s_changed = 0;
            __syncthreads();
            for (int i = tid; i < Nn; i += NT) {
                int c = comp[i]; int cc = comp[c];
                if (cc != c) { comp[i] = cc; s_changed = 1; }
            }
            __syncthreads();
            int chg = s_changed;
            __syncthreads();
            if (!chg) break;
        }
    }
    __syncthreads();

    // ---- phase 2: CSR build + BFS ----
    int* rowStart = (int*)(smem + 18240);
    int* adjList  = (int*)(smem + 55108);
    int* depth    = (int*)(smem + 128828);
    int* orderS   = (int*)(smem + 165692);

    for (int i = tid; i <= Nn; i += NT) rowStart[i] = 0;
    __syncthreads();
    for (int e = tid; e < Ee; e += NT) if (flag[e]) {
        int a, bn; edge_ep(e, a, bn);
        atomicAdd(&rowStart[a], 1);
        atomicAdd(&rowStart[bn], 1);
    }
    __syncthreads();
    // exclusive block scan over rowStart[0..Nn)
    {
        const int CHK = (Nn + NT - 1)/NT;  // 9
        int base = tid*CHK;
        int loc[9]; int sum = 0;
        for (int j = 0; j < CHK; j++) {
            int idx = base + j;
            int v = (idx < Nn) ? rowStart[idx] : 0;
            loc[j] = sum; sum += v;
        }
        depth[tid] = sum;
        __syncthreads();
        for (int off = 1; off < NT; off <<= 1) {
            int v = (tid >= off) ? depth[tid-off] : 0;
            __syncthreads();
            depth[tid] += v;
            __syncthreads();
        }
        int excl = (tid == 0) ? 0 : depth[tid-1];
        int total = depth[NT-1];
        __syncthreads();
        for (int j = 0; j < CHK; j++) {
            int idx = base + j;
            if (idx < Nn) rowStart[idx] = excl + loc[j];
        }
        if (tid == 0) rowStart[Nn] = total;
    }
    __syncthreads();
    // cursor = copy of rowStart (in depth[])
    for (int i = tid; i < Nn; i += NT) depth[i] = rowStart[i];
    __syncthreads();
    for (int e = tid; e < Ee; e += NT) if (flag[e]) {
        int a, bn; edge_ep(e, a, bn);
        int p = atomicAdd(&depth[a], 1);  adjList[p] = bn;
        int q = atomicAdd(&depth[bn], 1); adjList[q] = a;
    }
    __syncthreads();
    for (int i = tid; i < Nn; i += NT) depth[i] = -1;
    __syncthreads();
    if (tid == 0) {
        depth[0] = 0; orderS[0] = 0; s_head = 1;
        g_parent[t][b][0] = 0;
        g_levelStart[t][b][0] = 0;
        g_levelStart[t][b][1] = 1;
    }
    __syncthreads();
    int lvl = 0, lo = 0, hi = 1;
    while (hi > lo) {
        for (int k = lo + tid; k < hi; k += NT) {
            int u = orderS[k];
            int rs = rowStart[u], re = rowStart[u+1];
            for (int j = rs; j < re; j++) {
                int v = adjList[j];
                if (depth[v] < 0) {   // tree: unique predecessor per node -> race-free
                    depth[v] = lvl + 1;
                    g_parent[t][b][v] = u;
                    int p = atomicAdd(&s_head, 1);
                    orderS[p] = v;
                }
            }
        }
        __syncthreads();
        lvl++;
        lo = hi; hi = s_head;
        if (tid == 0) g_levelStart[t][b][lvl+1] = hi;
        __syncthreads();
    }
    if (tid == 0) g_nLevels[t][b] = lvl;
    for (int i = tid; i < Nn; i += NT) g_order[t][b][i] = orderS[i];
}

// ---------------- K4: per-node tree-edge weights exp(-d2/sigma) ----------------
__global__ void k_wnode(const float* __restrict__ low, const float* __restrict__ high) {
    int i = blockIdx.x*blockDim.x + threadIdx.x;
    int t = blockIdx.y, b = blockIdx.z;
    if (i >= Nn) return;
    int p = g_parent[t][b][i];
    const float* f = t ? (high + (size_t)b*CHh*Nn) : (low + (size_t)b*CL*Nn);
    int C = t ? CHh : CL;
    float inv_sig = t ? 1.0f : 50.0f;   // sigma=1.0 (high), 0.02 (low)
    float acc = 0.0f;
    for (int c = 0; c < C; c++) {
        float d = f[(size_t)c*Nn + i] - f[(size_t)c*Nn + p];
        acc += d*d;
    }
    g_wnode[t][b][i] = (i == 0) ? 0.0f : expf(-acc*inv_sig);
}

// ---------------- K5/K6: tree filter DP (one block per (b, channel)) ----------------
// shared: a[Nn] s[Nn] w[Nn] (float) + par[Nn] ord[Nn] (int) = 184320 B
#define FILT_SMEM 184320

__global__ void __launch_bounds__(1024,1) k_filter(int pass) {
    extern __shared__ unsigned char smem[];
    float* a = (float*)smem;
    float* s = a + Nn;
    float* w = s + Nn;
    int* par = (int*)(w + Nn);
    int* ord = par + Nn;

    const int t = pass - 1;
    const float* in = (pass == 1) ? g_prob : g_F1;
    const int cs = (pass == 1) ? CCn : 22;
    float* out = (pass == 1) ? g_F1 : g_F2;
    const bool normalize = (pass == 2);

    const int b = blockIdx.x / 22, ch = blockIdx.x % 22;
    const int tid = threadIdx.x, NT = blockDim.x;

    for (int i = tid; i < Nn; i += NT) {
        float v;
        if (ch < CCn) {
            v = in[((size_t)b*cs + ch)*Nn + i];
            if (normalize) v /= in[((size_t)b*cs + CCn)*Nn + i];
        } else v = 1.0f;
        a[i] = v;
        w[i] = g_wnode[t][b][i];
        par[i] = g_parent[t][b][i];
        ord[i] = g_order[t][b][i];
    }
    __syncthreads();

    const int nLev = g_nLevels[t][b];
    const int* LS = g_levelStart[t][b];

    // up: leaf -> root (within a level: reads level-d, writes level-(d-1): disjoint)
    for (int lev = nLev - 1; lev >= 1; lev--) {
        int lo = LS[lev], hi = LS[lev+1];
        for (int k = lo + tid; k < hi; k += NT) {
            int u = ord[k];
            atomicAdd(&a[par[u]], w[u]*a[u]);
        }
        __syncthreads();
    }
    for (int i = tid; i < Nn; i += NT) s[i] = a[i];
    __syncthreads();
    // down: root -> leaf
    for (int lev = 1; lev < nLev; lev++) {
        int lo = LS[lev], hi = LS[lev+1];
        for (int k = lo + tid; k < hi; k += NT) {
            int u = ord[k];
            float wu = w[u];
            s[u] = a[u] + wu*(s[par[u]] - wu*a[u]);
        }
        __syncthreads();
    }
    for (int i = tid; i < Nn; i += NT) out[((size_t)b*22 + ch)*Nn + i] = s[i];
}

// ---------------- K7: loss reduction ----------------
__global__ void k_loss(const float* __restrict__ roi) {
    __shared__ double red[256];
    long stride = (long)gridDim.x*blockDim.x;
    double ls = 0.0, ns = 0.0;
    for (long i = (long)blockIdx.x*blockDim.x + threadIdx.x; i < (long)Bq*CCn*Nn; i += stride) {
        int p = (int)(i % Nn);
        long bc = i / Nn;
        int c = (int)(bc % CCn);
        int b = (int)(bc / CCn);
        int row = p / Ww, col = p - row*Ww;
        float rv = roi[(size_t)b*(2*Hh)*(2*Ww) + (size_t)(2*row)*(2*Ww) + 2*col];
        float norm = g_F2[((size_t)b*22 + CCn)*Nn + p];
        float as = g_F2[((size_t)b*22 + c)*Nn + p] / norm;
        float pr = g_prob[i];
        ls += (double)(rv * fabsf(pr - as));
        if (c == 0) ns += (double)rv;
    }
    red[threadIdx.x] = ls; __syncthreads();
    for (int o = 128; o > 0; o >>= 1) { if (threadIdx.x < o) red[threadIdx.x] += red[threadIdx.x+o]; __syncthreads(); }
    if (threadIdx.x == 0) atomicAdd(&g_acc[0], red[0]);
    __syncthreads();
    red[threadIdx.x] = ns; __syncthreads();
    for (int o = 128; o > 0; o >>= 1) { if (threadIdx.x < o) red[threadIdx.x] += red[threadIdx.x+o]; __syncthreads(); }
    if (threadIdx.x == 0) atomicAdd(&g_acc[1], red[0]);
}

__global__ void k_final(float* out) {
    out[0] = (g_acc[1] > 0.0) ? (float)(g_acc[0]/g_acc[1]) : 0.0f;
}

// ---------------- launch ----------------
extern "C" void kernel_launch(void* const* d_in, const int* in_sizes, int n_in,
                              void* d_out, int out_size) {
    const float* preds = (const float*)d_in[0];
    const float* low   = (const float*)d_in[1];
    const float* high  = (const float*)d_in[2];
    const float* roi   = (const float*)d_in[3];
    float* out = (float*)d_out;

    cudaFuncSetAttribute(k_mst_bfs, cudaFuncAttributeMaxDynamicSharedMemorySize, MST_SMEM);
    cudaFuncSetAttribute(k_filter,  cudaFuncAttributeMaxDynamicSharedMemorySize, FILT_SMEM);

    k_prep<<<(Bq*CCn*Nn + 255)/256, 256>>>(preds);
    k_edgew<<<dim3((Ee + 127)/128, 2, Bq), 128>>>(low, high);
    k_mst_bfs<<<8, 1024, MST_SMEM>>>();
    k_wnode<<<dim3((Nn + 127)/128, 2, Bq), 128>>>(low, high);
    k_filter<<<Bq*22, 1024, FILT_SMEM>>>(1);
    k_filter<<<Bq*22, 1024, FILT_SMEM>>>(2);
    k_loss<<<512, 256>>>(roi);
    k_final<<<1, 1>>>(out);
}

// round 4
// speedup vs baseline: 1.4341x; 1.4341x over previous
#include <cuda_runtime.h>
#include <math.h>

// Problem constants
#define Bq 4
#define CCn 21
#define Hh 96
#define Ww 96
#define Nn (Hh*Ww)          // 9216
#define EH (Hh*(Ww-1))      // 9120
#define EV ((Hh-1)*Ww)      // 9120
#define Ee (EH+EV)          // 18240
#define CL 3
#define CHh 512

// ---- device scratch (static, no allocation) ----
__device__ float g_prob[Bq*CCn*Nn];
__device__ float g_part[Bq][8][Ee];          // per-chunk fp32 partial edge weights (high)
__device__ float g_wE[2][Bq][Ee];
__device__ int   g_parent[2][Bq][Nn];
__device__ int   g_order[2][Bq][Nn];         // node id at BFS position k
__device__ int   g_pp[2][Bq][Nn];            // BFS position of parent, per position k
__device__ float g_Wp[2][Bq][Nn];            // edge weight exp(-d2/sigma), per position k
__device__ int   g_levelStart[2][Bq][Nn+2];
__device__ int   g_nLevels[2][Bq];
__device__ float g_F1[Bq*22*Nn];
__device__ float g_F2[Bq*22*Nn];
__device__ double g_acc[2];

__device__ __forceinline__ void edge_ep(int e, int& a, int& b) {
    if (e < EH) { int r = e / (Ww-1); int c = e - r*(Ww-1); a = r*Ww + c; b = a + 1; }
    else        { int e2 = e - EH;    a = e2;               b = e2 + Ww; }
}

// ---------------- K1: sigmoid + zero accumulators ----------------
__global__ void k_prep(const float* __restrict__ preds) {
    int i = blockIdx.x*blockDim.x + threadIdx.x;
    if (blockIdx.x == 0 && threadIdx.x == 0) { g_acc[0] = 0.0; g_acc[1] = 0.0; }
    if (i < Bq*CCn*Nn) g_prob[i] = 1.0f/(1.0f + expf(-preds[i]));
}

// ---------------- K2a: low-tree edge weights (C=3, exact fp64) ----------------
__global__ void k_edgew_low(const float* __restrict__ low) {
    int e = blockIdx.x*blockDim.x + threadIdx.x;
    int b = blockIdx.y;
    if (e >= Ee) return;
    int a, bn; edge_ep(e, a, bn);
    const float* f = low + (size_t)b*CL*Nn;
    double acc = 0.0;
    #pragma unroll
    for (int c = 0; c < CL; c++) {
        double d = (double)f[c*Nn + a] - (double)f[c*Nn + bn];
        acc += d*d;
    }
    g_wE[0][b][e] = (float)acc;
}

// ---------------- K2b: high-tree partials (fp32, 64-ch chunks) ----------------
__global__ void k_edgew_hi_part(const float* __restrict__ high) {
    int e = blockIdx.x*blockDim.x + threadIdx.x;
    if (e >= Ee) return;
    int chunk = blockIdx.y, b = blockIdx.z;
    int a, bn; edge_ep(e, a, bn);
    const float* f = high + ((size_t)b*CHh + (size_t)chunk*64)*Nn;
    float acc = 0.0f;
    #pragma unroll 8
    for (int c = 0; c < 64; c++) {
        float d = __ldg(&f[(size_t)c*Nn + a]) - __ldg(&f[(size_t)c*Nn + bn]);
        acc = fmaf(d, d, acc);
    }
    g_part[b][chunk][e] = acc;
}

// ---------------- K2c: combine chunks in fp64 (deterministic) ----------------
__global__ void k_edgew_hi_reduce() {
    int e = blockIdx.x*blockDim.x + threadIdx.x;
    int b = blockIdx.y;
    if (e >= Ee) return;
    double s = 0.0;
    #pragma unroll
    for (int c = 0; c < 8; c++) s += (double)g_part[b][c][e];
    g_wE[1][b][e] = (float)s;
}

// ---------------- K3: Boruvka MST + CSR + BFS (one block per (t,b)) ----------------
// phase1 smem (all disjoint):
//  flag   [0,      18240)   uchar[Ee]
//  comp   [18240,  55104)   int[Nn]
//  best   [55104, 128832)   u64[Nn]   (8-aligned)
//  active [128832,201792)   int[Ee]   (in-place compaction via register staging)
// phase2 smem (flag persists; rest reused):
//  rowStart [18240, 55108)  int[Nn+1]
//  adjList  [55108,128828)  int[2*(Nn-1)]
//  depth    [128832,165696) int[Nn]
//  orderS   [165696,202560) int[Nn]
#define MST_SMEM 202560

__global__ void __launch_bounds__(1024,1) k_mst_bfs() {
    extern __shared__ unsigned char smem[];
    const int t = blockIdx.x >> 2, b = blockIdx.x & 3;
    const int tid = threadIdx.x, NT = blockDim.x;

    unsigned char* flag = smem;
    int* comp = (int*)(smem + 18240);
    unsigned long long* best = (unsigned long long*)(smem + 55104);
    int* active = (int*)(smem + 128832);

    __shared__ int s_merged, s_changed, s_head, s_cnt;
    const float* wptr = g_wE[t][b];

    for (int e = tid; e < Ee; e += NT) { flag[e] = 0; active[e] = e; }
    for (int i = tid; i < Nn; i += NT) comp[i] = i;
    if (tid == 0) s_cnt = Ee;
    __syncthreads();

    // ---- Boruvka rounds ----
    for (int round = 0; round < 16; round++) {
        int cnt = s_cnt;
        if (cnt == 0) break;
        for (int i = tid; i < Nn; i += NT) best[i] = 0xFFFFFFFFFFFFFFFFULL;
        if (tid == 0) { s_merged = 0; }
        __syncthreads();

        // scan active edges; collect survivors in registers (<= ceil(Ee/NT) = 18)
        int surv[18]; int nSurv = 0;
        for (int idx = tid; idx < cnt; idx += NT) {
            int e = active[idx];
            int a, bn; edge_ep(e, a, bn);
            int ca = comp[a], cb = comp[bn];
            if (ca != cb) {
                unsigned long long key =
                    ((unsigned long long)__float_as_uint(__ldg(&wptr[e])) << 32) | (unsigned)e;
                atomicMin(&best[ca], key);
                atomicMin(&best[cb], key);
                surv[nSurv++] = e;
            }
        }
        __syncthreads();
        if (tid == 0) s_cnt = 0;
        __syncthreads();

        // hooking phase A (read-only decide) + in-place survivor writeback
        int myRoot[10], myOther[10], myEdge[10]; int nMy = 0;
        for (int i = tid; i < Nn; i += NT) {
            if (comp[i] == i && best[i] != 0xFFFFFFFFFFFFFFFFULL) {
                unsigned long long k = best[i];
                int e = (int)(k & 0xFFFFFFFFu);
                int a, bn; edge_ep(e, a, bn);
                int ca = comp[a], cb = comp[bn];
                int other = (ca == i) ? cb : ca;
                bool mutual = (best[other] == k);
                if (!mutual || other < i) {
                    myRoot[nMy] = i; myOther[nMy] = other; myEdge[nMy] = e; nMy++;
                }
            }
        }
        if (nSurv) {
            int base = atomicAdd(&s_cnt, nSurv);
            for (int j = 0; j < nSurv; j++) active[base + j] = surv[j];
        }
        __syncthreads();
        // hooking phase B (write)
        for (int j = 0; j < nMy; j++) { comp[myRoot[j]] = myOther[j]; flag[myEdge[j]] = 1; }
        if (nMy) s_merged = 1;
        __syncthreads();
        int m = s_merged;
        __syncthreads();
        if (!m) break;
        // pointer jumping to full compression
        for (;;) {
            if (tid == 0) s_changed = 0;
            __syncthreads();
            for (int i = tid; i < Nn; i += NT) {
                int c = comp[i]; int cc = comp[c];
                if (cc != c) { comp[i] = cc; s_changed = 1; }
            }
            __syncthreads();
            int chg = s_changed;
            __syncthreads();
            if (!chg) break;
        }
    }
    __syncthreads();

    // ---- phase 2: CSR build + BFS ----
    int* rowStart = (int*)(smem + 18240);
    int* adjList  = (int*)(smem + 55108);
    int* depth    = (int*)(smem + 128832);
    int* orderS   = (int*)(smem + 165696);

    for (int i = tid; i <= Nn; i += NT) rowStart[i] = 0;
    __syncthreads();
    for (int e = tid; e < Ee; e += NT) if (flag[e]) {
        int a, bn; edge_ep(e, a, bn);
        atomicAdd(&rowStart[a], 1);
        atomicAdd(&rowStart[bn], 1);
    }
    __syncthreads();
    // exclusive block scan over rowStart[0..Nn)
    {
        const int CHK = (Nn + NT - 1)/NT;  // 9
        int base = tid*CHK;
        int loc[9]; int sum = 0;
        #pragma unroll
        for (int j = 0; j < CHK; j++) {
            int idx = base + j;
            int v = (idx < Nn) ? rowStart[idx] : 0;
            loc[j] = sum; sum += v;
        }
        depth[tid] = sum;
        __syncthreads();
        for (int off = 1; off < NT; off <<= 1) {
            int v = (tid >= off) ? depth[tid-off] : 0;
            __syncthreads();
            depth[tid] += v;
            __syncthreads();
        }
        int excl = (tid == 0) ? 0 : depth[tid-1];
        int total = depth[NT-1];
        __syncthreads();
        #pragma unroll
        for (int j = 0; j < CHK; j++) {
            int idx = base + j;
            if (idx < Nn) rowStart[idx] = excl + loc[j];
        }
        if (tid == 0) rowStart[Nn] = total;
    }
    __syncthreads();
    // cursor = copy of rowStart (in depth[])
    for (int i = tid; i < Nn; i += NT) depth[i] = rowStart[i];
    __syncthreads();
    for (int e = tid; e < Ee; e += NT) if (flag[e]) {
        int a, bn; edge_ep(e, a, bn);
        int p = atomicAdd(&depth[a], 1);  adjList[p] = bn;
        int q = atomicAdd(&depth[bn], 1); adjList[q] = a;
    }
    __syncthreads();
    for (int i = tid; i < Nn; i += NT) depth[i] = -1;
    __syncthreads();
    if (tid == 0) {
        depth[0] = 0; orderS[0] = 0; s_head = 1;
        g_parent[t][b][0] = 0;
        g_pp[t][b][0] = 0;
        g_levelStart[t][b][0] = 0;
        g_levelStart[t][b][1] = 1;
    }
    __syncthreads();
    // ---- single-warp level-synchronous BFS (no block barriers in the chain) ----
    if (tid < 32) {
        int lvl = 0, lo = 0, hi = 1;
        while (hi > lo) {
            for (int k = lo + tid; k < hi; k += 32) {
                int u = orderS[k];
                int rs = rowStart[u], re = rowStart[u+1];
                for (int j = rs; j < re; j++) {
                    int v = adjList[j];
                    if (depth[v] < 0) {   // tree: unique predecessor -> race-free
                        depth[v] = 1;
                        int p = atomicAdd(&s_head, 1);
                        orderS[p] = v;
                        g_parent[t][b][v] = u;
                        g_pp[t][b][p] = k;
                    }
                }
            }
            __syncwarp();
            lvl++;
            lo = hi; hi = s_head;
            if (tid == 0) g_levelStart[t][b][lvl+1] = hi;
            __syncwarp();
        }
        if (tid == 0) g_nLevels[t][b] = lvl;
    }
    __syncthreads();
    for (int i = tid; i < Nn; i += NT) g_order[t][b][i] = orderS[i];
}

// ---------------- K4: permuted tree-edge weights from g_wE ----------------
__global__ void k_wnode() {
    int k = blockIdx.x*blockDim.x + threadIdx.x;
    int t = blockIdx.y, b = blockIdx.z;
    if (k >= Nn) return;
    float Wv = 0.0f;
    if (k > 0) {
        int v = g_order[t][b][k];
        int p = g_parent[t][b][v];
        int d = v - p;
        int e;
        if (d == 1)       { int r = v / Ww, c = v - r*Ww; e = r*(Ww-1) + (c-1); }
        else if (d == -1) { int r = v / Ww, c = v - r*Ww; e = r*(Ww-1) + c; }
        else if (d == Ww) { e = EH + p; }
        else              { e = EH + v; }
        float inv_sig = t ? 1.0f : 50.0f;   // sigma = 1.0 (high), 0.02 (low)
        Wv = expf(-g_wE[t][b][e]*inv_sig);
    }
    g_Wp[t][b][k] = Wv;
}

// ---------------- K5/K6: tree filter DP in BFS-order space ----------------
// smem: A[Nn], W[Nn] (float) + PP[Nn], ORD[Nn] (int) + sLS[Nn+2]
#define FILT_SMEM 184336
#define FNT 128

__global__ void __launch_bounds__(FNT,1) k_filter(int pass) {
    extern __shared__ unsigned char smem[];
    float* A  = (float*)smem;
    float* W  = A + Nn;
    int* PP   = (int*)(W + Nn);
    int* ORD  = PP + Nn;
    int* sLS  = ORD + Nn;

    const int t = pass - 1;
    const float* in = (pass == 1) ? g_prob : g_F1;
    const int cs = (pass == 1) ? CCn : 22;
    float* out = (pass == 1) ? g_F1 : g_F2;
    const bool normalize = (pass == 2);

    const int b = blockIdx.x / 22, ch = blockIdx.x % 22;
    const int tid = threadIdx.x;

    const int nLev = g_nLevels[t][b];
    const float* inb = in + (size_t)b*cs*Nn;
    const float* inn = in + ((size_t)b*cs + CCn)*Nn;

    for (int k = tid; k < Nn; k += FNT) {
        int v = g_order[t][b][k];
        ORD[k] = v;
        PP[k] = g_pp[t][b][k];
        W[k] = g_Wp[t][b][k];
        float val;
        if (ch < CCn) {
            val = inb[(size_t)ch*Nn + v];
            if (normalize) val /= inn[v];
        } else val = 1.0f;
        A[k] = val;
    }
    for (int l = tid; l < nLev + 2; l += FNT) sLS[l] = g_levelStart[t][b][l];
    __syncthreads();

    // up: leaf -> root
    for (int lev = nLev - 1; lev >= 1; lev--) {
        int lo = sLS[lev], hi = sLS[lev+1];
        if (hi - lo <= 32) {
            if (tid < 32) {
                int k = lo + tid;
                if (k < hi) atomicAdd(&A[PP[k]], W[k]*A[k]);
                __syncwarp();
            }
        } else {
            __syncthreads();
            for (int k = lo + tid; k < hi; k += FNT) atomicAdd(&A[PP[k]], W[k]*A[k]);
            __syncthreads();
        }
    }
    __syncthreads();
    // down: root -> leaf, in place: A[k] = A[k] + W[k]*(A[pp] - W[k]*A[k])
    for (int lev = 1; lev < nLev; lev++) {
        int lo = sLS[lev], hi = sLS[lev+1];
        if (hi - lo <= 32) {
            if (tid < 32) {
                int k = lo + tid;
                if (k < hi) {
                    float wk = W[k], ak = A[k];
                    A[k] = fmaf(wk, A[PP[k]] - wk*ak, ak);
                }
                __syncwarp();
            }
        } else {
            __syncthreads();
            for (int k = lo + tid; k < hi; k += FNT) {
                float wk = W[k], ak = A[k];
                A[k] = fmaf(wk, A[PP[k]] - wk*ak, ak);
            }
            __syncthreads();
        }
    }
    __syncthreads();
    float* outb = out + (size_t)(b*22 + ch)*Nn;
    for (int k = tid; k < Nn; k += FNT) outb[ORD[k]] = A[k];
}

// ---------------- K7: loss reduction ----------------
__global__ void k_loss(const float* __restrict__ roi) {
    __shared__ double red[256];
    long stride = (long)gridDim.x*blockDim.x;
    double ls = 0.0, ns = 0.0;
    for (long i = (long)blockIdx.x*blockDim.x + threadIdx.x; i < (long)Bq*CCn*Nn; i += stride) {
        int p = (int)(i % Nn);
        long bc = i / Nn;
        int c = (int)(bc % CCn);
        int b = (int)(bc / CCn);
        int row = p / Ww, col = p - row*Ww;
        float rv = roi[(size_t)b*(2*Hh)*(2*Ww) + (size_t)(2*row)*(2*Ww) + 2*col];
        float norm = g_F2[((size_t)b*22 + CCn)*Nn + p];
        float as = g_F2[((size_t)b*22 + c)*Nn + p] / norm;
        float pr = g_prob[i];
        ls += (double)(rv * fabsf(pr - as));
        if (c == 0) ns += (double)rv;
    }
    red[threadIdx.x] = ls; __syncthreads();
    for (int o = 128; o > 0; o >>= 1) { if (threadIdx.x < o) red[threadIdx.x] += red[threadIdx.x+o]; __syncthreads(); }
    if (threadIdx.x == 0) atomicAdd(&g_acc[0], red[0]);
    __syncthreads();
    red[threadIdx.x] = ns; __syncthreads();
    for (int o = 128; o > 0; o >>= 1) { if (threadIdx.x < o) red[threadIdx.x] += red[threadIdx.x+o]; __syncthreads(); }
    if (threadIdx.x == 0) atomicAdd(&g_acc[1], red[0]);
}

__global__ void k_final(float* out) {
    out[0] = (g_acc[1] > 0.0) ? (float)(g_acc[0]/g_acc[1]) : 0.0f;
}

// ---------------- launch ----------------
extern "C" void kernel_launch(void* const* d_in, const int* in_sizes, int n_in,
                              void* d_out, int out_size) {
    const float* preds = (const float*)d_in[0];
    const float* low   = (const float*)d_in[1];
    const float* high  = (const float*)d_in[2];
    const float* roi   = (const float*)d_in[3];
    float* out = (float*)d_out;

    cudaFuncSetAttribute(k_mst_bfs, cudaFuncAttributeMaxDynamicSharedMemorySize, MST_SMEM);
    cudaFuncSetAttribute(k_filter,  cudaFuncAttributeMaxDynamicSharedMemorySize, FILT_SMEM);

    k_prep<<<(Bq*CCn*Nn + 255)/256, 256>>>(preds);
    k_edgew_low<<<dim3((Ee + 127)/128, Bq), 128>>>(low);
    k_edgew_hi_part<<<dim3((Ee + 127)/128, 8, Bq), 128>>>(high);
    k_edgew_hi_reduce<<<dim3((Ee + 255)/256, Bq), 256>>>();
    k_mst_bfs<<<8, 1024, MST_SMEM>>>();
    k_wnode<<<dim3((Nn + 127)/128, 2, Bq), 128>>>();
    k_filter<<<Bq*22, FNT, FILT_SMEM>>>(1);
    k_filter<<<Bq*22, FNT, FILT_SMEM>>>(2);
    k_loss<<<512, 256>>>(roi);
    k_final<<<1, 1>>>(out);
}

// round 6
// speedup vs baseline: 1.4544x; 1.0142x over previous
#include <cuda_runtime.h>
#include <math.h>

// Problem constants
#define Bq 4
#define CCn 21
#define Hh 96
#define Ww 96
#define Nn (Hh*Ww)          // 9216
#define EH (Hh*(Ww-1))      // 9120
#define EV ((Hh-1)*Ww)      // 9120
#define Ee (EH+EV)          // 18240
#define CL 3
#define CHh 512

// ---- device scratch (static, no allocation) ----
__device__ float g_prob[Bq*CCn*Nn];
__device__ float g_part[Bq][8][Ee];          // per-chunk fp32 partial edge weights (high)
__device__ float g_wE[2][Bq][Ee];
__device__ int   g_parent[2][Bq][Nn];
__device__ int   g_order[2][Bq][Nn];         // node id at BFS position k
__device__ int   g_pp[2][Bq][Nn];            // BFS position of parent, per position k
__device__ float g_Wp[2][Bq][Nn];            // edge weight exp(-d2/sigma), per position k
__device__ int   g_levelStart[2][Bq][Nn+2];
__device__ int   g_nLevels[2][Bq];
__device__ float g_F1[Bq*22*Nn];
__device__ float g_F2[Bq*22*Nn];
__device__ double g_acc[2];

__device__ __forceinline__ void edge_ep(int e, int& a, int& b) {
    if (e < EH) { int r = e / (Ww-1); int c = e - r*(Ww-1); a = r*Ww + c; b = a + 1; }
    else        { int e2 = e - EH;    a = e2;               b = e2 + Ww; }
}

// ---------------- K1: sigmoid + zero accumulators ----------------
__global__ void k_prep(const float* __restrict__ preds) {
    int i = blockIdx.x*blockDim.x + threadIdx.x;
    if (blockIdx.x == 0 && threadIdx.x == 0) { g_acc[0] = 0.0; g_acc[1] = 0.0; }
    if (i < Bq*CCn*Nn) g_prob[i] = 1.0f/(1.0f + expf(-preds[i]));
}

// ---------------- K2a: low-tree edge weights (C=3, exact fp64) ----------------
__global__ void k_edgew_low(const float* __restrict__ low) {
    int e = blockIdx.x*blockDim.x + threadIdx.x;
    int b = blockIdx.y;
    if (e >= Ee) return;
    int a, bn; edge_ep(e, a, bn);
    const float* f = low + (size_t)b*CL*Nn;
    double acc = 0.0;
    #pragma unroll
    for (int c = 0; c < CL; c++) {
        double d = (double)f[c*Nn + a] - (double)f[c*Nn + bn];
        acc += d*d;
    }
    g_wE[0][b][e] = (float)acc;
}

// ---------------- K2b: high-tree partials (fp32, 64-ch chunks, 4-way ILP) ----------------
__global__ void k_edgew_hi_part(const float* __restrict__ high) {
    int e = blockIdx.x*blockDim.x + threadIdx.x;
    if (e >= Ee) return;
    int chunk = blockIdx.y, b = blockIdx.z;
    int a, bn; edge_ep(e, a, bn);
    const float* f = high + ((size_t)b*CHh + (size_t)chunk*64)*Nn;
    float a0 = 0.f, a1 = 0.f, a2 = 0.f, a3 = 0.f;
    #pragma unroll
    for (int c = 0; c < 64; c += 4) {
        float d0 = __ldg(&f[(size_t)(c+0)*Nn + a]) - __ldg(&f[(size_t)(c+0)*Nn + bn]);
        float d1 = __ldg(&f[(size_t)(c+1)*Nn + a]) - __ldg(&f[(size_t)(c+1)*Nn + bn]);
        float d2 = __ldg(&f[(size_t)(c+2)*Nn + a]) - __ldg(&f[(size_t)(c+2)*Nn + bn]);
        float d3 = __ldg(&f[(size_t)(c+3)*Nn + a]) - __ldg(&f[(size_t)(c+3)*Nn + bn]);
        a0 = fmaf(d0, d0, a0);
        a1 = fmaf(d1, d1, a1);
        a2 = fmaf(d2, d2, a2);
        a3 = fmaf(d3, d3, a3);
    }
    g_part[b][chunk][e] = (a0 + a1) + (a2 + a3);
}

// ---------------- K2c: combine chunks in fp64 (deterministic) ----------------
__global__ void k_edgew_hi_reduce() {
    int e = blockIdx.x*blockDim.x + threadIdx.x;
    int b = blockIdx.y;
    if (e >= Ee) return;
    double s = 0.0;
    #pragma unroll
    for (int c = 0; c < 8; c++) s += (double)g_part[b][c][e];
    g_wE[1][b][e] = (float)s;
}

// ---------------- K3: Boruvka MST + CSR + BFS + Wp (one block per (t,b)) ----------------
// phase1 smem (all disjoint):
//  flag   [0,      18240)   uchar[Ee]
//  comp   [18240,  55104)   int[Nn]
//  best   [55104, 128832)   u64[Nn]   (8-aligned)
//  active [128832,201792)   int[Ee]   (in-place compaction via register staging)
// phase2 smem (flag persists; rest reused):
//  rowStart [18240, 55108)  int[Nn+1]
//  adjList  [55108,128828)  int[2*(Nn-1)]
//  depth    [128832,165696) int[Nn]
//  orderS   [165696,202560) int[Nn]
#define MST_SMEM 202560

__global__ void __launch_bounds__(1024,1) k_mst_bfs() {
    extern __shared__ unsigned char smem[];
    const int t = blockIdx.x >> 2, b = blockIdx.x & 3;
    const int tid = threadIdx.x, NT = blockDim.x;

    unsigned char* flag = smem;
    int* comp = (int*)(smem + 18240);
    unsigned long long* best = (unsigned long long*)(smem + 55104);
    int* active = (int*)(smem + 128832);

    __shared__ int s_merged, s_head, s_cnt[2];
    const float* wptr = g_wE[t][b];

    for (int e = tid; e < Ee; e += NT) { flag[e] = 0; active[e] = e; }
    for (int i = tid; i < Nn; i += NT) comp[i] = i;
    if (tid == 0) { s_cnt[0] = Ee; }
    __syncthreads();

    // ---- Boruvka rounds (5 block barriers per round) ----
    for (int round = 0; round < 16; round++) {
        const int p = round & 1;
        int cnt = s_cnt[p];
        if (cnt == 0) break;
        for (int i = tid; i < Nn; i += NT) best[i] = 0xFFFFFFFFFFFFFFFFULL;
        if (tid == 0) { s_merged = 0; s_cnt[p^1] = 0; }
        __syncthreads();                                   // B1

        // scan active edges; collect survivors in registers (<= ceil(Ee/NT) = 18)
        int surv[18]; int nSurv = 0;
        for (int idx = tid; idx < cnt; idx += NT) {
            int e = active[idx];
            int a, bn; edge_ep(e, a, bn);
            int ca = comp[a], cb = comp[bn];
            if (ca != cb) {
                unsigned long long key =
                    ((unsigned long long)__float_as_uint(__ldg(&wptr[e])) << 32) | (unsigned)e;
                atomicMin(&best[ca], key);
                atomicMin(&best[cb], key);
                surv[nSurv++] = e;
            }
        }
        __syncthreads();                                   // B2

        // hooking decide (read-only) + in-place survivor writeback
        int myRoot[10], myOther[10], myEdge[10]; int nMy = 0;
        for (int i = tid; i < Nn; i += NT) {
            if (comp[i] == i && best[i] != 0xFFFFFFFFFFFFFFFFULL) {
                unsigned long long k = best[i];
                int e = (int)(k & 0xFFFFFFFFu);
                int a, bn; edge_ep(e, a, bn);
                int ca = comp[a], cb = comp[bn];
                int other = (ca == i) ? cb : ca;
                bool mutual = (best[other] == k);
                if (!mutual || other < i) {
                    myRoot[nMy] = i; myOther[nMy] = other; myEdge[nMy] = e; nMy++;
                }
            }
        }
        if (nSurv) {
            int base = atomicAdd(&s_cnt[p^1], nSurv);
            for (int j = 0; j < nSurv; j++) active[base + j] = surv[j];
        }
        __syncthreads();                                   // B3
        // hooking write
        for (int j = 0; j < nMy; j++) { comp[myRoot[j]] = myOther[j]; flag[myEdge[j]] = 1; }
        if (nMy) s_merged = 1;
        __syncthreads();                                   // B4
        if (!s_merged) break;
        // barrier-free full compression: chase to root (all writes point to ancestors)
        for (int i = tid; i < Nn; i += NT) {
            int r = comp[i];
            int rr = comp[r];
            while (rr != r) { r = rr; rr = comp[r]; }
            comp[i] = r;
        }
        __syncthreads();                                   // B5
    }
    __syncthreads();

    // ---- phase 2: CSR build + BFS ----
    int* rowStart = (int*)(smem + 18240);
    int* adjList  = (int*)(smem + 55108);
    int* depth    = (int*)(smem + 128832);
    int* orderS   = (int*)(smem + 165696);

    for (int i = tid; i <= Nn; i += NT) rowStart[i] = 0;
    __syncthreads();
    for (int e = tid; e < Ee; e += NT) if (flag[e]) {
        int a, bn; edge_ep(e, a, bn);
        atomicAdd(&rowStart[a], 1);
        atomicAdd(&rowStart[bn], 1);
    }
    __syncthreads();
    // exclusive block scan over rowStart[0..Nn)
    {
        const int CHK = (Nn + NT - 1)/NT;  // 9
        int base = tid*CHK;
        int loc[9]; int sum = 0;
        #pragma unroll
        for (int j = 0; j < CHK; j++) {
            int idx = base + j;
            int v = (idx < Nn) ? rowStart[idx] : 0;
            loc[j] = sum; sum += v;
        }
        depth[tid] = sum;
        __syncthreads();
        for (int off = 1; off < NT; off <<= 1) {
            int v = (tid >= off) ? depth[tid-off] : 0;
            __syncthreads();
            depth[tid] += v;
            __syncthreads();
        }
        int excl = (tid == 0) ? 0 : depth[tid-1];
        int total = depth[NT-1];
        __syncthreads();
        #pragma unroll
        for (int j = 0; j < CHK; j++) {
            int idx = base + j;
            if (idx < Nn) rowStart[idx] = excl + loc[j];
        }
        if (tid == 0) rowStart[Nn] = total;
    }
    __syncthreads();
    // cursor = copy of rowStart (in depth[])
    for (int i = tid; i < Nn; i += NT) depth[i] = rowStart[i];
    __syncthreads();
    for (int e = tid; e < Ee; e += NT) if (flag[e]) {
        int a, bn; edge_ep(e, a, bn);
        int p = atomicAdd(&depth[a], 1);  adjList[p] = bn;
        int q = atomicAdd(&depth[bn], 1); adjList[q] = a;
    }
    __syncthreads();
    for (int i = tid; i < Nn; i += NT) depth[i] = -1;
    __syncthreads();
    if (tid == 0) {
        depth[0] = 0; orderS[0] = 0; s_head = 1;
        g_parent[t][b][0] = 0;
        g_pp[t][b][0] = 0;
        g_levelStart[t][b][0] = 0;
        g_levelStart[t][b][1] = 1;
    }
    __syncthreads();
    // ---- single-warp level-synchronous BFS (no block barriers in the chain) ----
    if (tid < 32) {
        int lvl = 0, lo = 0, hi = 1;
        while (hi > lo) {
            for (int k = lo + tid; k < hi; k += 32) {
                int u = orderS[k];
                int rs = rowStart[u], re = rowStart[u+1];
                for (int j = rs; j < re; j++) {
                    int v = adjList[j];
                    if (depth[v] < 0) {   // tree: unique predecessor -> race-free
                        depth[v] = 1;
                        int p = atomicAdd(&s_head, 1);
                        orderS[p] = v;
                        g_parent[t][b][v] = u;
                        g_pp[t][b][p] = k;
                    }
                }
            }
            __syncwarp();
            lvl++;
            lo = hi; hi = s_head;
            if (tid == 0) g_levelStart[t][b][lvl+1] = hi;
            __syncwarp();
        }
        if (tid == 0) g_nLevels[t][b] = lvl;
    }
    __syncthreads();
    // ---- fused wnode: order writeback + per-position edge weight exp(-d2/sigma) ----
    const float inv_sig = t ? 1.0f : 50.0f;   // sigma = 1.0 (high), 0.02 (low)
    for (int k = tid; k < Nn; k += NT) {
        int v = orderS[k];
        g_order[t][b][k] = v;
        float Wv = 0.0f;
        if (k > 0) {
            int pn = g_parent[t][b][v];
            int d = v - pn;
            int e;
            if (d == 1)       { int r = v / Ww, c = v - r*Ww; e = r*(Ww-1) + (c-1); }
            else if (d == -1) { int r = v / Ww, c = v - r*Ww; e = r*(Ww-1) + c; }
            else if (d == Ww) { e = EH + pn; }
            else              { e = EH + v; }
            Wv = expf(-__ldg(&wptr[e])*inv_sig);
        }
        g_Wp[t][b][k] = Wv;
    }
}

// ---------------- K5/K6: tree filter DP in BFS-order space ----------------
// smem: A[Nn], W[Nn] (float) + PP[Nn], ORD[Nn] (int) + sLS[Nn+2]
#define FILT_SMEM 184336
#define FNT 128

__global__ void __launch_bounds__(FNT,1) k_filter(int pass) {
    extern __shared__ unsigned char smem[];
    float* A  = (float*)smem;
    float* W  = A + Nn;
    int* PP   = (int*)(W + Nn);
    int* ORD  = PP + Nn;
    int* sLS  = ORD + Nn;

    const int t = pass - 1;
    const float* in = (pass == 1) ? g_prob : g_F1;
    const int cs = (pass == 1) ? CCn : 22;
    float* out = (pass == 1) ? g_F1 : g_F2;
    const bool normalize = (pass == 2);

    const int b = blockIdx.x / 22, ch = blockIdx.x % 22;
    const int tid = threadIdx.x;

    const int nLev = g_nLevels[t][b];
    const float* inb = in + (size_t)b*cs*Nn;
    const float* inn = in + ((size_t)b*cs + CCn)*Nn;

    for (int k = tid; k < Nn; k += FNT) {
        int v = g_order[t][b][k];
        ORD[k] = v;
        PP[k] = g_pp[t][b][k];
        W[k] = g_Wp[t][b][k];
        float val;
        if (ch < CCn) {
            val = inb[(size_t)ch*Nn + v];
            if (normalize) val /= inn[v];
        } else val = 1.0f;
        A[k] = val;
    }
    for (int l = tid; l < nLev + 2; l += FNT) sLS[l] = g_levelStart[t][b][l];
    __syncthreads();

    // up: leaf -> root
    for (int lev = nLev - 1; lev >= 1; lev--) {
        int lo = sLS[lev], hi = sLS[lev+1];
        if (hi - lo <= 32) {
            if (tid < 32) {
                int k = lo + tid;
                if (k < hi) atomicAdd(&A[PP[k]], W[k]*A[k]);
                __syncwarp();
            }
        } else {
            __syncthreads();
            for (int k = lo + tid; k < hi; k += FNT) atomicAdd(&A[PP[k]], W[k]*A[k]);
            __syncthreads();
        }
    }
    __syncthreads();
    // down: root -> leaf, in place: A[k] = A[k] + W[k]*(A[pp] - W[k]*A[k])
    for (int lev = 1; lev < nLev; lev++) {
        int lo = sLS[lev], hi = sLS[lev+1];
        if (hi - lo <= 32) {
            if (tid < 32) {
                int k = lo + tid;
                if (k < hi) {
                    float wk = W[k], ak = A[k];
                    A[k] = fmaf(wk, A[PP[k]] - wk*ak, ak);
                }
                __syncwarp();
            }
        } else {
            __syncthreads();
            for (int k = lo + tid; k < hi; k += FNT) {
                float wk = W[k], ak = A[k];
                A[k] = fmaf(wk, A[PP[k]] - wk*ak, ak);
            }
            __syncthreads();
        }
    }
    __syncthreads();
    float* outb = out + (size_t)(b*22 + ch)*Nn;
    for (int k = tid; k < Nn; k += FNT) outb[ORD[k]] = A[k];
}

// ---------------- K7: loss reduction ----------------
__global__ void k_loss(const float* __restrict__ roi) {
    __shared__ double red[256];
    long stride = (long)gridDim.x*blockDim.x;
    double ls = 0.0, ns = 0.0;
    for (long i = (long)blockIdx.x*blockDim.x + threadIdx.x; i < (long)Bq*CCn*Nn; i += stride) {
        int p = (int)(i % Nn);
        long bc = i / Nn;
        int c = (int)(bc % CCn);
        int b = (int)(bc / CCn);
        int row = p / Ww, col = p - row*Ww;
        float rv = roi[(size_t)b*(2*Hh)*(2*Ww) + (size_t)(2*row)*(2*Ww) + 2*col];
        float norm = g_F2[((size_t)b*22 + CCn)*Nn + p];
        float as = g_F2[((size_t)b*22 + c)*Nn + p] / norm;
        float pr = g_prob[i];
        ls += (double)(rv * fabsf(pr - as));
        if (c == 0) ns += (double)rv;
    }
    red[threadIdx.x] = ls; __syncthreads();
    for (int o = 128; o > 0; o >>= 1) { if (threadIdx.x < o) red[threadIdx.x] += red[threadIdx.x+o]; __syncthreads(); }
    if (threadIdx.x == 0) atomicAdd(&g_acc[0], red[0]);
    __syncthreads();
    red[threadIdx.x] = ns; __syncthreads();
    for (int o = 128; o > 0; o >>= 1) { if (threadIdx.x < o) red[threadIdx.x] += red[threadIdx.x+o]; __syncthreads(); }
    if (threadIdx.x == 0) atomicAdd(&g_acc[1], red[0]);
}

__global__ void k_final(float* out) {
    out[0] = (g_acc[1] > 0.0) ? (float)(g_acc[0]/g_acc[1]) : 0.0f;
}

// ---------------- launch (mst at idx 3 so ncu profiles it) ----------------
extern "C" void kernel_launch(void* const* d_in, const int* in_sizes, int n_in,
                              void* d_out, int out_size) {
    const float* preds = (const float*)d_in[0];
    const float* low   = (const float*)d_in[1];
    const float* high  = (const float*)d_in[2];
    const float* roi   = (const float*)d_in[3];
    float* out = (float*)d_out;

    cudaFuncSetAttribute(k_mst_bfs, cudaFuncAttributeMaxDynamicSharedMemorySize, MST_SMEM);
    cudaFuncSetAttribute(k_filter,  cudaFuncAttributeMaxDynamicSharedMemorySize, FILT_SMEM);

    k_edgew_hi_part<<<dim3((Ee + 127)/128, 8, Bq), 128>>>(high);   // idx0
    k_edgew_low<<<dim3((Ee + 127)/128, Bq), 128>>>(low);           // idx1
    k_edgew_hi_reduce<<<dim3((Ee + 255)/256, Bq), 256>>>();        // idx2
    k_mst_bfs<<<8, 1024, MST_SMEM>>>();                            // idx3 <- profiled
    k_prep<<<(Bq*CCn*Nn + 255)/256, 256>>>(preds);                 // idx4
    k_filter<<<Bq*22, FNT, FILT_SMEM>>>(1);                        // idx5
    k_filter<<<Bq*22, FNT, FILT_SMEM>>>(2);                        // idx6
    k_loss<<<512, 256>>>(roi);                                     // idx7
    k_final<<<1, 1>>>(out);                                        // idx8
}

// round 11
// speedup vs baseline: 1.5129x; 1.0402x over previous
#include <cuda_runtime.h>
#include <math.h>

// Problem constants
#define Bq 4
#define CCn 21
#define Hh 96
#define Ww 96
#define Nn (Hh*Ww)          // 9216
#define EH (Hh*(Ww-1))      // 9120
#define EV ((Hh-1)*Ww)      // 9120
#define Ee (EH+EV)          // 18240
#define CL 3
#define CHh 512
#define ROOT (48*Ww + 48)   // center root: tree filter is root-invariant; halves BFS depth

// ---- device scratch (static, no allocation) ----
__device__ float g_prob[Bq*CCn*Nn];
__device__ float g_part[Bq][8][Ee];
__device__ float g_wE[2][Bq][Ee];
__device__ unsigned char g_flag[2][Bq][Ee];  // MST edge markers (boruvka -> bfs handoff)
__device__ int   g_parent[2][Bq][Nn];
__device__ int   g_order[2][Bq][Nn];         // node id at BFS position k
__device__ int   g_pp[2][Bq][Nn];            // BFS position of parent, per position k
__device__ float g_Wp[2][Bq][Nn];            // edge weight exp(-d2/sigma), per position k
__device__ int   g_levelStart[2][Bq][Nn+2];
__device__ int   g_nLevels[2][Bq];
__device__ float g_F1[Bq*22*Nn];
__device__ float g_F2[Bq*22*Nn];
__device__ double g_acc[2];

__device__ __forceinline__ void edge_ep(int e, int& a, int& b) {
    if (e < EH) { int r = e / (Ww-1); int c = e - r*(Ww-1); a = r*Ww + c; b = a + 1; }
    else        { int e2 = e - EH;    a = e2;               b = e2 + Ww; }
}

// ---------------- K1: sigmoid + zero accumulators ----------------
__global__ void k_prep(const float* __restrict__ preds) {
    int i = blockIdx.x*blockDim.x + threadIdx.x;
    if (blockIdx.x == 0 && threadIdx.x == 0) { g_acc[0] = 0.0; g_acc[1] = 0.0; }
    if (i < Bq*CCn*Nn) g_prob[i] = 1.0f/(1.0f + expf(-preds[i]));
}

// ---------------- K2a: low-tree edge weights (C=3, exact fp64) ----------------
__global__ void k_edgew_low(const float* __restrict__ low) {
    int e = blockIdx.x*blockDim.x + threadIdx.x;
    int b = blockIdx.y;
    if (e >= Ee) return;
    int a, bn; edge_ep(e, a, bn);
    const float* f = low + (size_t)b*CL*Nn;
    double acc = 0.0;
    #pragma unroll
    for (int c = 0; c < CL; c++) {
        double d = (double)f[c*Nn + a] - (double)f[c*Nn + bn];
        acc += d*d;
    }
    g_wE[0][b][e] = (float)acc;
}

// ---------------- K2b: high-tree partials (fp32, 64-ch chunks, 4-way ILP) ----------------
__global__ void k_edgew_hi_part(const float* __restrict__ high) {
    int e = blockIdx.x*blockDim.x + threadIdx.x;
    if (e >= Ee) return;
    int chunk = blockIdx.y, b = blockIdx.z;
    int a, bn; edge_ep(e, a, bn);
    const float* f = high + ((size_t)b*CHh + (size_t)chunk*64)*Nn;
    float a0 = 0.f, a1 = 0.f, a2 = 0.f, a3 = 0.f;
    #pragma unroll
    for (int c = 0; c < 64; c += 4) {
        float d0 = __ldg(&f[(size_t)(c+0)*Nn + a]) - __ldg(&f[(size_t)(c+0)*Nn + bn]);
        float d1 = __ldg(&f[(size_t)(c+1)*Nn + a]) - __ldg(&f[(size_t)(c+1)*Nn + bn]);
        float d2 = __ldg(&f[(size_t)(c+2)*Nn + a]) - __ldg(&f[(size_t)(c+2)*Nn + bn]);
        float d3 = __ldg(&f[(size_t)(c+3)*Nn + a]) - __ldg(&f[(size_t)(c+3)*Nn + bn]);
        a0 = fmaf(d0, d0, a0);
        a1 = fmaf(d1, d1, a1);
        a2 = fmaf(d2, d2, a2);
        a3 = fmaf(d3, d3, a3);
    }
    g_part[b][chunk][e] = (a0 + a1) + (a2 + a3);
}

// ---------------- K2c: combine chunks in fp64 (deterministic) ----------------
__global__ void k_edgew_hi_reduce() {
    int e = blockIdx.x*blockDim.x + threadIdx.x;
    int b = blockIdx.y;
    if (e >= Ee) return;
    double s = 0.0;
    #pragma unroll
    for (int c = 0; c < 8; c++) s += (double)g_part[b][c][e];
    g_wE[1][b][e] = (float)s;
}

// ---------------- K3a: Boruvka MST (one block per (t,b)) ----------------
// smem: comp[0,36864) int[Nn] | best[36864,110592) u64[Nn] | active[110592,183552) int[Ee]
#define MST1_SMEM 183552

__global__ void __launch_bounds__(1024,1) k_boruvka() {
    extern __shared__ unsigned char smem[];
    const int t = blockIdx.x >> 2, b = blockIdx.x & 3;
    const int tid = threadIdx.x, NT = blockDim.x;

    int* comp = (int*)smem;
    unsigned long long* best = (unsigned long long*)(smem + 36864);
    int* active = (int*)(smem + 110592);
    unsigned char* flag = g_flag[t][b];

    __shared__ int s_merged, s_cnt[2];
    const float* wptr = g_wE[t][b];

    for (int e = tid; e < Ee; e += NT) { flag[e] = 0; active[e] = e; }
    for (int i = tid; i < Nn; i += NT) comp[i] = i;
    if (tid == 0) { s_cnt[0] = Ee; }
    __syncthreads();

    for (int round = 0; round < 16; round++) {
        const int p = round & 1;
        int cnt = s_cnt[p];
        if (cnt == 0) break;
        for (int i = tid; i < Nn; i += NT) best[i] = 0xFFFFFFFFFFFFFFFFULL;
        if (tid == 0) { s_merged = 0; s_cnt[p^1] = 0; }
        __syncthreads();                                   // B1

        int surv[18]; int nSurv = 0;
        for (int idx = tid; idx < cnt; idx += NT) {
            int e = active[idx];
            int a, bn; edge_ep(e, a, bn);
            int ca = comp[a], cb = comp[bn];
            if (ca != cb) {
                unsigned long long key =
                    ((unsigned long long)__float_as_uint(__ldg(&wptr[e])) << 32) | (unsigned)e;
                atomicMin(&best[ca], key);
                atomicMin(&best[cb], key);
                surv[nSurv++] = e;
            }
        }
        __syncthreads();                                   // B2

        int myRoot[10], myOther[10], myEdge[10]; int nMy = 0;
        for (int i = tid; i < Nn; i += NT) {
            if (comp[i] == i && best[i] != 0xFFFFFFFFFFFFFFFFULL) {
                unsigned long long k = best[i];
                int e = (int)(k & 0xFFFFFFFFu);
                int a, bn; edge_ep(e, a, bn);
                int ca = comp[a], cb = comp[bn];
                int other = (ca == i) ? cb : ca;
                bool mutual = (best[other] == k);
                if (!mutual || other < i) {
                    myRoot[nMy] = i; myOther[nMy] = other; myEdge[nMy] = e; nMy++;
                }
            }
        }
        if (nSurv) {
            int base = atomicAdd(&s_cnt[p^1], nSurv);
            for (int j = 0; j < nSurv; j++) active[base + j] = surv[j];
        }
        __syncthreads();                                   // B3
        for (int j = 0; j < nMy; j++) { comp[myRoot[j]] = myOther[j]; flag[myEdge[j]] = 1; }
        if (nMy) s_merged = 1;
        __syncthreads();                                   // B4
        if (!s_merged) break;
        // barrier-free full compression: chase to root (writes always point to ancestors)
        for (int i = tid; i < Nn; i += NT) {
            int r = comp[i];
            int rr = comp[r];
            while (rr != r) { r = rr; rr = comp[r]; }
            comp[i] = r;
        }
        __syncthreads();                                   // B5
    }
}

// ---------------- K3b: CSR + BFS (center root) + Wp (one block per (t,b)) ----------------
// smem: rowStart[0,36868) | adjList[36868,110588) | depth[110588,147452) | orderS[147452,184316)
#define MST2_SMEM 184320

__global__ void __launch_bounds__(1024,1) k_bfs() {
    extern __shared__ unsigned char smem[];
    const int t = blockIdx.x >> 2, b = blockIdx.x & 3;
    const int tid = threadIdx.x, NT = blockDim.x;

    int* rowStart = (int*)smem;
    int* adjList  = (int*)(smem + 36868);
    int* depth    = (int*)(smem + 110588);
    int* orderS   = (int*)(smem + 147452);
    const unsigned char* flag = g_flag[t][b];
    const float* wptr = g_wE[t][b];
    __shared__ int s_head;

    for (int i = tid; i <= Nn; i += NT) rowStart[i] = 0;
    __syncthreads();
    for (int e = tid; e < Ee; e += NT) if (flag[e]) {
        int a, bn; edge_ep(e, a, bn);
        atomicAdd(&rowStart[a], 1);
        atomicAdd(&rowStart[bn], 1);
    }
    __syncthreads();
    // exclusive block scan over rowStart[0..Nn)
    {
        const int CHK = (Nn + NT - 1)/NT;  // 9
        int base = tid*CHK;
        int loc[9]; int sum = 0;
        #pragma unroll
        for (int j = 0; j < CHK; j++) {
            int idx = base + j;
            int v = (idx < Nn) ? rowStart[idx] : 0;
            loc[j] = sum; sum += v;
        }
        depth[tid] = sum;
        __syncthreads();
        for (int off = 1; off < NT; off <<= 1) {
            int v = (tid >= off) ? depth[tid-off] : 0;
            __syncthreads();
            depth[tid] += v;
            __syncthreads();
        }
        int excl = (tid == 0) ? 0 : depth[tid-1];
        int total = depth[NT-1];
        __syncthreads();
        #pragma unroll
        for (int j = 0; j < CHK; j++) {
            int idx = base + j;
            if (idx < Nn) rowStart[idx] = excl + loc[j];
        }
        if (tid == 0) rowStart[Nn] = total;
    }
    __syncthreads();
    for (int i = tid; i < Nn; i += NT) depth[i] = rowStart[i];   // cursor
    __syncthreads();
    for (int e = tid; e < Ee; e += NT) if (flag[e]) {
        int a, bn; edge_ep(e, a, bn);
        int p = atomicAdd(&depth[a], 1);  adjList[p] = bn;
        int q = atomicAdd(&depth[bn], 1); adjList[q] = a;
    }
    __syncthreads();
    for (int i = tid; i < Nn; i += NT) depth[i] = -1;
    __syncthreads();
    if (tid == 0) {
        depth[ROOT] = 0; orderS[0] = ROOT; s_head = 1;
        g_parent[t][b][ROOT] = ROOT;
        g_pp[t][b][0] = 0;
        g_levelStart[t][b][0] = 0;
        g_levelStart[t][b][1] = 1;
    }
    __syncthreads();
    // ---- single-warp level-synchronous BFS ----
    if (tid < 32) {
        int lvl = 0, lo = 0, hi = 1;
        while (hi > lo) {
            for (int k = lo + tid; k < hi; k += 32) {
                int u = orderS[k];
                int rs = rowStart[u], re = rowStart[u+1];
                for (int j = rs; j < re; j++) {
                    int v = adjList[j];
                    if (depth[v] < 0) {   // tree: unique predecessor -> race-free
                        depth[v] = 1;
                        int p = atomicAdd(&s_head, 1);
                        orderS[p] = v;
                        g_parent[t][b][v] = u;
                        g_pp[t][b][p] = k;
                    }
                }
            }
            __syncwarp();
            lvl++;
            lo = hi; hi = s_head;
            if (tid == 0) g_levelStart[t][b][lvl+1] = hi;
            __syncwarp();
        }
        if (tid == 0) g_nLevels[t][b] = lvl;
    }
    __syncthreads();
    // ---- fused wnode: order writeback + per-position edge weight exp(-d2/sigma) ----
    const float inv_sig = t ? 1.0f : 50.0f;   // sigma = 1.0 (high), 0.02 (low)
    for (int k = tid; k < Nn; k += NT) {
        int v = orderS[k];
        g_order[t][b][k] = v;
        float Wv = 0.0f;
        if (k > 0) {
            int pn = g_parent[t][b][v];
            int d = v - pn;
            int e;
            if (d == 1)       { int r = v / Ww, c = v - r*Ww; e = r*(Ww-1) + (c-1); }
            else if (d == -1) { int r = v / Ww, c = v - r*Ww; e = r*(Ww-1) + c; }
            else if (d == Ww) { e = EH + pn; }
            else              { e = EH + v; }
            Wv = expf(-__ldg(&wptr[e])*inv_sig);
        }
        g_Wp[t][b][k] = Wv;
    }
}

// ---------------- K5/K6: tree filter DP in BFS-order space ----------------
#define FILT_SMEM 184336
#define FNT 128

__global__ void __launch_bounds__(FNT,1) k_filter(int pass) {
    extern __shared__ unsigned char smem[];
    float* A  = (float*)smem;
    float* W  = A + Nn;
    int* PP   = (int*)(W + Nn);
    int* ORD  = PP + Nn;
    int* sLS  = ORD + Nn;

    const int t = pass - 1;
    const float* in = (pass == 1) ? g_prob : g_F1;
    const int cs = (pass == 1) ? CCn : 22;
    float* out = (pass == 1) ? g_F1 : g_F2;
    const bool normalize = (pass == 2);

    const int b = blockIdx.x / 22, ch = blockIdx.x % 22;
    const int tid = threadIdx.x;

    const int nLev = g_nLevels[t][b];
    const float* inb = in + (size_t)b*cs*Nn;
    const float* inn = in + ((size_t)b*cs + CCn)*Nn;

    for (int k = tid; k < Nn; k += FNT) {
        int v = g_order[t][b][k];
        ORD[k] = v;
        PP[k] = g_pp[t][b][k];
        W[k] = g_Wp[t][b][k];
        float val;
        if (ch < CCn) {
            val = inb[(size_t)ch*Nn + v];
            if (normalize) val /= inn[v];
        } else val = 1.0f;
        A[k] = val;
    }
    for (int l = tid; l < nLev + 2; l += FNT) sLS[l] = g_levelStart[t][b][l];
    __syncthreads();

    // up: leaf -> root
    for (int lev = nLev - 1; lev >= 1; lev--) {
        int lo = sLS[lev], hi = sLS[lev+1];
        if (hi - lo <= 32) {
            if (tid < 32) {
                int k = lo + tid;
                if (k < hi) atomicAdd(&A[PP[k]], W[k]*A[k]);
                __syncwarp();
            }
        } else {
            __syncthreads();
            for (int k = lo + tid; k < hi; k += FNT) atomicAdd(&A[PP[k]], W[k]*A[k]);
            __syncthreads();
        }
    }
    __syncthreads();
    // down: root -> leaf, in place
    for (int lev = 1; lev < nLev; lev++) {
        int lo = sLS[lev], hi = sLS[lev+1];
        if (hi - lo <= 32) {
            if (tid < 32) {
                int k = lo + tid;
                if (k < hi) {
                    float wk = W[k], ak = A[k];
                    A[k] = fmaf(wk, A[PP[k]] - wk*ak, ak);
                }
                __syncwarp();
            }
        } else {
            __syncthreads();
            for (int k = lo + tid; k < hi; k += FNT) {
                float wk = W[k], ak = A[k];
                A[k] = fmaf(wk, A[PP[k]] - wk*ak, ak);
            }
            __syncthreads();
        }
    }
    __syncthreads();
    float* outb = out + (size_t)(b*22 + ch)*Nn;
    for (int k = tid; k < Nn; k += FNT) outb[ORD[k]] = A[k];
}

// ---------------- K7: loss reduction ----------------
__global__ void k_loss(const float* __restrict__ roi) {
    __shared__ double red[256];
    long stride = (long)gridDim.x*blockDim.x;
    double ls = 0.0, ns = 0.0;
    for (long i = (long)blockIdx.x*blockDim.x + threadIdx.x; i < (long)Bq*CCn*Nn; i += stride) {
        int p = (int)(i % Nn);
        long bc = i / Nn;
        int c = (int)(bc % CCn);
        int b = (int)(bc / CCn);
        int row = p / Ww, col = p - row*Ww;
        float rv = roi[(size_t)b*(2*Hh)*(2*Ww) + (size_t)(2*row)*(2*Ww) + 2*col];
        float norm = g_F2[((size_t)b*22 + CCn)*Nn + p];
        float as = g_F2[((size_t)b*22 + c)*Nn + p] / norm;
        float pr = g_prob[i];
        ls += (double)(rv * fabsf(pr - as));
        if (c == 0) ns += (double)rv;
    }
    red[threadIdx.x] = ls; __syncthreads();
    for (int o = 128; o > 0; o >>= 1) { if (threadIdx.x < o) red[threadIdx.x] += red[threadIdx.x+o]; __syncthreads(); }
    if (threadIdx.x == 0) atomicAdd(&g_acc[0], red[0]);
    __syncthreads();
    red[threadIdx.x] = ns; __syncthreads();
    for (int o = 128; o > 0; o >>= 1) { if (threadIdx.x < o) red[threadIdx.x] += red[threadIdx.x+o]; __syncthreads(); }
    if (threadIdx.x == 0) atomicAdd(&g_acc[1], red[0]);
}

__global__ void k_final(float* out) {
    out[0] = (g_acc[1] > 0.0) ? (float)(g_acc[0]/g_acc[1]) : 0.0f;
}

// ---------------- launch (k_boruvka at idx 3 -> profiled) ----------------
extern "C" void kernel_launch(void* const* d_in, const int* in_sizes, int n_in,
                              void* d_out, int out_size) {
    const float* preds = (const float*)d_in[0];
    const float* low   = (const float*)d_in[1];
    const float* high  = (const float*)d_in[2];
    const float* roi   = (const float*)d_in[3];
    float* out = (float*)d_out;

    cudaFuncSetAttribute(k_boruvka, cudaFuncAttributeMaxDynamicSharedMemorySize, MST1_SMEM);
    cudaFuncSetAttribute(k_bfs,     cudaFuncAttributeMaxDynamicSharedMemorySize, MST2_SMEM);
    cudaFuncSetAttribute(k_filter,  cudaFuncAttributeMaxDynamicSharedMemorySize, FILT_SMEM);

    k_edgew_hi_part<<<dim3((Ee + 127)/128, 8, Bq), 128>>>(high);   // idx0
    k_edgew_low<<<dim3((Ee + 127)/128, Bq), 128>>>(low);           // idx1
    k_edgew_hi_reduce<<<dim3((Ee + 255)/256, Bq), 256>>>();        // idx2
    k_boruvka<<<8, 1024, MST1_SMEM>>>();                           // idx3 <- profiled
    k_bfs<<<8, 1024, MST2_SMEM>>>();                               // idx4
    k_prep<<<(Bq*CCn*Nn + 255)/256, 256>>>(preds);                 // idx5
    k_filter<<<Bq*22, FNT, FILT_SMEM>>>(1);                        // idx6
    k_filter<<<Bq*22, FNT, FILT_SMEM>>>(2);                        // idx7
    k_loss<<<512, 256>>>(roi);                                     // idx8
    k_final<<<1, 1>>>(out);                                        // idx9
}

// round 12
// speedup vs baseline: 1.8654x; 1.2331x over previous
#include <cuda_runtime.h>
#include <math.h>

// Problem constants
#define Bq 4
#define CCn 21
#define Hh 96
#define Ww 96
#define Nn (Hh*Ww)          // 9216
#define EH (Hh*(Ww-1))      // 9120
#define EV ((Hh-1)*Ww)      // 9120
#define Ee (EH+EV)          // 18240
#define CL 3
#define CHh 512
#define ROOT (48*Ww + 48)   // center root: tree filter is root-invariant; halves BFS depth

// ---- device scratch (static, no allocation) ----
__device__ float g_prob[Bq*CCn*Nn];
__device__ float g_part[Bq][8][Ee];
__device__ float g_wE[2][Bq][Ee];
__device__ unsigned char g_flag[2][Bq][Ee];  // MST edge markers (boruvka -> bfs handoff)
__device__ int   g_order[2][Bq][Nn];         // node id at BFS position k
__device__ int   g_pp[2][Bq][Nn];            // BFS position of parent, per position k
__device__ float g_Wp[2][Bq][Nn];            // edge weight exp(-d2/sigma), per position k
__device__ int   g_levelStart[2][Bq][Nn+2];
__device__ int   g_nLevels[2][Bq];
__device__ float g_F1[Bq*22*Nn];
__device__ float g_F2[Bq*22*Nn];
__device__ double g_acc[2];

__device__ __forceinline__ void edge_ep(int e, int& a, int& b) {
    if (e < EH) { int r = e / (Ww-1); int c = e - r*(Ww-1); a = r*Ww + c; b = a + 1; }
    else        { int e2 = e - EH;    a = e2;               b = e2 + Ww; }
}

// ---------------- K1: sigmoid + zero accumulators ----------------
__global__ void k_prep(const float* __restrict__ preds) {
    int i = blockIdx.x*blockDim.x + threadIdx.x;
    if (blockIdx.x == 0 && threadIdx.x == 0) { g_acc[0] = 0.0; g_acc[1] = 0.0; }
    if (i < Bq*CCn*Nn) g_prob[i] = 1.0f/(1.0f + expf(-preds[i]));
}

// ---------------- K2a: high-tree partials (fp32, 64-ch chunks, 4-way ILP) ----------------
__global__ void k_edgew_hi_part(const float* __restrict__ high) {
    int e = blockIdx.x*blockDim.x + threadIdx.x;
    if (e >= Ee) return;
    int chunk = blockIdx.y, b = blockIdx.z;
    int a, bn; edge_ep(e, a, bn);
    const float* f = high + ((size_t)b*CHh + (size_t)chunk*64)*Nn;
    float a0 = 0.f, a1 = 0.f, a2 = 0.f, a3 = 0.f;
    #pragma unroll
    for (int c = 0; c < 64; c += 4) {
        float d0 = __ldg(&f[(size_t)(c+0)*Nn + a]) - __ldg(&f[(size_t)(c+0)*Nn + bn]);
        float d1 = __ldg(&f[(size_t)(c+1)*Nn + a]) - __ldg(&f[(size_t)(c+1)*Nn + bn]);
        float d2 = __ldg(&f[(size_t)(c+2)*Nn + a]) - __ldg(&f[(size_t)(c+2)*Nn + bn]);
        float d3 = __ldg(&f[(size_t)(c+3)*Nn + a]) - __ldg(&f[(size_t)(c+3)*Nn + bn]);
        a0 = fmaf(d0, d0, a0);
        a1 = fmaf(d1, d1, a1);
        a2 = fmaf(d2, d2, a2);
        a3 = fmaf(d3, d3, a3);
    }
    g_part[b][chunk][e] = (a0 + a1) + (a2 + a3);
}

// ---------------- K2b: fp64 chunk combine (high) + low-tree weights, fused ----------------
__global__ void k_edgew_reduce_low(const float* __restrict__ low) {
    int e = blockIdx.x*blockDim.x + threadIdx.x;
    int b = blockIdx.y;
    if (e >= Ee) return;
    double s = 0.0;
    #pragma unroll
    for (int c = 0; c < 8; c++) s += (double)g_part[b][c][e];
    g_wE[1][b][e] = (float)s;
    int a, bn; edge_ep(e, a, bn);
    const float* f = low + (size_t)b*CL*Nn;
    double acc = 0.0;
    #pragma unroll
    for (int c = 0; c < CL; c++) {
        double d = (double)f[c*Nn + a] - (double)f[c*Nn + bn];
        acc += d*d;
    }
    g_wE[0][b][e] = (float)acc;
}

// ---------------- K3a: Boruvka MST (one block per (t,b)) ----------------
// smem: comp[0,36864) int[Nn] | best[36864,110592) u64[Nn] | active[110592,183552) int[Ee]
#define MST1_SMEM 183552

__global__ void __launch_bounds__(1024,1) k_boruvka() {
    extern __shared__ unsigned char smem[];
    const int t = blockIdx.x >> 2, b = blockIdx.x & 3;
    const int tid = threadIdx.x, NT = blockDim.x;

    int* comp = (int*)smem;
    unsigned long long* best = (unsigned long long*)(smem + 36864);
    int* active = (int*)(smem + 110592);
    unsigned char* flag = g_flag[t][b];

    __shared__ int s_merged, s_cnt[2];
    const float* wptr = g_wE[t][b];

    for (int e = tid; e < Ee; e += NT) { flag[e] = 0; active[e] = e; }
    for (int i = tid; i < Nn; i += NT) comp[i] = i;
    if (tid == 0) { s_cnt[0] = Ee; }
    __syncthreads();

    for (int round = 0; round < 16; round++) {
        const int p = round & 1;
        int cnt = s_cnt[p];
        if (cnt == 0) break;
        for (int i = tid; i < Nn; i += NT) best[i] = 0xFFFFFFFFFFFFFFFFULL;
        if (tid == 0) { s_merged = 0; s_cnt[p^1] = 0; }
        __syncthreads();                                   // B1

        int surv[18]; int nSurv = 0;
        for (int idx = tid; idx < cnt; idx += NT) {
            int e = active[idx];
            int a, bn; edge_ep(e, a, bn);
            int ca = comp[a], cb = comp[bn];
            if (ca != cb) {
                unsigned long long key =
                    ((unsigned long long)__float_as_uint(__ldg(&wptr[e])) << 32) | (unsigned)e;
                atomicMin(&best[ca], key);
                atomicMin(&best[cb], key);
                surv[nSurv++] = e;
            }
        }
        __syncthreads();                                   // B2

        int myRoot[10], myOther[10], myEdge[10]; int nMy = 0;
        for (int i = tid; i < Nn; i += NT) {
            if (comp[i] == i && best[i] != 0xFFFFFFFFFFFFFFFFULL) {
                unsigned long long k = best[i];
                int e = (int)(k & 0xFFFFFFFFu);
                int a, bn; edge_ep(e, a, bn);
                int ca = comp[a], cb = comp[bn];
                int other = (ca == i) ? cb : ca;
                bool mutual = (best[other] == k);
                if (!mutual || other < i) {
                    myRoot[nMy] = i; myOther[nMy] = other; myEdge[nMy] = e; nMy++;
                }
            }
        }
        if (nSurv) {
            int base = atomicAdd(&s_cnt[p^1], nSurv);
            for (int j = 0; j < nSurv; j++) active[base + j] = surv[j];
        }
        __syncthreads();                                   // B3
        for (int j = 0; j < nMy; j++) { comp[myRoot[j]] = myOther[j]; flag[myEdge[j]] = 1; }
        if (nMy) s_merged = 1;
        __syncthreads();                                   // B4
        if (!s_merged) break;
        // barrier-free full compression: chase to root (writes always point to ancestors)
        for (int i = tid; i < Nn; i += NT) {
            int r = comp[i];
            int rr = comp[r];
            while (rr != r) { r = rr; rr = comp[r]; }
            comp[i] = r;
        }
        __syncthreads();                                   // B5
    }
}

// ---------------- K3b: mask-based BFS (center root) + Wp (one block per (t,b)) ----------------
// Tree on 4-connected grid: children(v) = direction-mask(v) minus incoming direction.
// No CSR, no visited array, no adjacency loads in the serial chain.
// dir bits: 0=E(+1) 1=W(-1) 2=S(+Ww) 3=N(-Ww); incoming-at-child = d^1.
// smem: mask[0,36864) | packed[36864,73728) | pp_s[73728,110592) | eid[110592,147456)
#define BFS_SMEM 147456

__global__ void __launch_bounds__(1024,1) k_bfs() {
    extern __shared__ unsigned char smem[];
    const int t = blockIdx.x >> 2, b = blockIdx.x & 3;
    const int tid = threadIdx.x, NT = blockDim.x;

    int* mask   = (int*)smem;
    int* packed = (int*)(smem + 36864);   // node | incomingDir<<14
    int* pp_s   = (int*)(smem + 73728);
    int* eid    = (int*)(smem + 110592);
    const unsigned char* flag = g_flag[t][b];
    const float* wptr = g_wE[t][b];
    __shared__ int s_head;

    for (int i = tid; i < Nn; i += NT) mask[i] = 0;
    __syncthreads();
    for (int e = tid; e < Ee; e += NT) if (flag[e]) {
        int a, bn; edge_ep(e, a, bn);
        if (e < EH) { atomicOr(&mask[a], 1); atomicOr(&mask[bn], 2); }
        else        { atomicOr(&mask[a], 4); atomicOr(&mask[bn], 8); }
    }
    __syncthreads();
    if (tid == 0) {
        packed[0] = ROOT | (4 << 14);   // incoming dir 4 = none; bits 0-3 unaffected
        pp_s[0] = 0;
        eid[0] = 0;
        s_head = 1;
        g_levelStart[t][b][0] = 0;
        g_levelStart[t][b][1] = 1;
    }
    __syncthreads();

    // ---- single-warp level-synchronous BFS, mask-driven ----
    if (tid < 32) {
        int lvl = 0, lo = 0, hi = 1;
        while (hi > lo) {
            for (int k = lo + tid; k < hi; k += 32) {
                int pk = packed[k];
                int v = pk & 0x3FFF;
                int m = mask[v] & ~(1 << (pk >> 14));
                if (m) {
                    int base = atomicAdd(&s_head, __popc(m));
                    int r = v / Ww, cc = v - r*Ww;
                    while (m) {
                        int d = __ffs(m) - 1; m &= m - 1;
                        int c, e;
                        if (d == 0)      { c = v + 1;  e = r*(Ww-1) + cc; }
                        else if (d == 1) { c = v - 1;  e = r*(Ww-1) + cc - 1; }
                        else if (d == 2) { c = v + Ww; e = EH + v; }
                        else             { c = v - Ww; e = EH + v - Ww; }
                        packed[base] = c | ((d ^ 1) << 14);
                        pp_s[base] = k;
                        eid[base] = e;
                        base++;
                    }
                }
            }
            __syncwarp();
            lvl++;
            lo = hi; hi = s_head;
            if (tid == 0) g_levelStart[t][b][lvl + 1] = hi;
            __syncwarp();
        }
        if (tid == 0) g_nLevels[t][b] = lvl;
    }
    __syncthreads();

    // ---- parallel tail: order/pp writeback + Wp = exp(-d2/sigma) ----
    const float inv_sig = t ? 1.0f : 50.0f;   // sigma = 1.0 (high), 0.02 (low)
    for (int k = tid; k < Nn; k += NT) {
        g_order[t][b][k] = packed[k] & 0x3FFF;
        g_pp[t][b][k] = pp_s[k];
        g_Wp[t][b][k] = (k > 0) ? expf(-__ldg(&wptr[eid[k]])*inv_sig) : 0.0f;
    }
}

// ---------------- K5/K6: tree filter DP in BFS-order space ----------------
#define FILT_SMEM 184336
#define FNT 128

__global__ void __launch_bounds__(FNT,1) k_filter(int pass) {
    extern __shared__ unsigned char smem[];
    float* A  = (float*)smem;
    float* W  = A + Nn;
    int* PP   = (int*)(W + Nn);
    int* ORD  = PP + Nn;
    int* sLS  = ORD + Nn;

    const int t = pass - 1;
    const float* in = (pass == 1) ? g_prob : g_F1;
    const int cs = (pass == 1) ? CCn : 22;
    float* out = (pass == 1) ? g_F1 : g_F2;
    const bool normalize = (pass == 2);

    const int b = blockIdx.x / 22, ch = blockIdx.x % 22;
    const int tid = threadIdx.x;

    const int nLev = g_nLevels[t][b];
    const float* inb = in + (size_t)b*cs*Nn;
    const float* inn = in + ((size_t)b*cs + CCn)*Nn;

    for (int k = tid; k < Nn; k += FNT) {
        int v = g_order[t][b][k];
        ORD[k] = v;
        PP[k] = g_pp[t][b][k];
        W[k] = g_Wp[t][b][k];
        float val;
        if (ch < CCn) {
            val = inb[(size_t)ch*Nn + v];
            if (normalize) val /= inn[v];
        } else val = 1.0f;
        A[k] = val;
    }
    for (int l = tid; l < nLev + 2; l += FNT) sLS[l] = g_levelStart[t][b][l];
    __syncthreads();

    // up: leaf -> root
    for (int lev = nLev - 1; lev >= 1; lev--) {
        int lo = sLS[lev], hi = sLS[lev+1];
        if (hi - lo <= 32) {
            if (tid < 32) {
                int k = lo + tid;
                if (k < hi) atomicAdd(&A[PP[k]], W[k]*A[k]);
                __syncwarp();
            }
        } else {
            __syncthreads();
            for (int k = lo + tid; k < hi; k += FNT) atomicAdd(&A[PP[k]], W[k]*A[k]);
            __syncthreads();
        }
    }
    __syncthreads();
    // down: root -> leaf, in place
    for (int lev = 1; lev < nLev; lev++) {
        int lo = sLS[lev], hi = sLS[lev+1];
        if (hi - lo <= 32) {
            if (tid < 32) {
                int k = lo + tid;
                if (k < hi) {
                    float wk = W[k], ak = A[k];
                    A[k] = fmaf(wk, A[PP[k]] - wk*ak, ak);
                }
                __syncwarp();
            }
        } else {
            __syncthreads();
            for (int k = lo + tid; k < hi; k += FNT) {
                float wk = W[k], ak = A[k];
                A[k] = fmaf(wk, A[PP[k]] - wk*ak, ak);
            }
            __syncthreads();
        }
    }
    __syncthreads();
    float* outb = out + (size_t)(b*22 + ch)*Nn;
    for (int k = tid; k < Nn; k += FNT) outb[ORD[k]] = A[k];
}

// ---------------- K7: loss reduction ----------------
__global__ void k_loss(const float* __restrict__ roi) {
    __shared__ double red[256];
    long stride = (long)gridDim.x*blockDim.x;
    double ls = 0.0, ns = 0.0;
    for (long i = (long)blockIdx.x*blockDim.x + threadIdx.x; i < (long)Bq*CCn*Nn; i += stride) {
        int p = (int)(i % Nn);
        long bc = i / Nn;
        int c = (int)(bc % CCn);
        int b = (int)(bc / CCn);
        int row = p / Ww, col = p - row*Ww;
        float rv = roi[(size_t)b*(2*Hh)*(2*Ww) + (size_t)(2*row)*(2*Ww) + 2*col];
        float norm = g_F2[((size_t)b*22 + CCn)*Nn + p];
        float as = g_F2[((size_t)b*22 + c)*Nn + p] / norm;
        float pr = g_prob[i];
        ls += (double)(rv * fabsf(pr - as));
        if (c == 0) ns += (double)rv;
    }
    red[threadIdx.x] = ls; __syncthreads();
    for (int o = 128; o > 0; o >>= 1) { if (threadIdx.x < o) red[threadIdx.x] += red[threadIdx.x+o]; __syncthreads(); }
    if (threadIdx.x == 0) atomicAdd(&g_acc[0], red[0]);
    __syncthreads();
    red[threadIdx.x] = ns; __syncthreads();
    for (int o = 128; o > 0; o >>= 1) { if (threadIdx.x < o) red[threadIdx.x] += red[threadIdx.x+o]; __syncthreads(); }
    if (threadIdx.x == 0) atomicAdd(&g_acc[1], red[0]);
}

__global__ void k_final(float* out) {
    out[0] = (g_acc[1] > 0.0) ? (float)(g_acc[0]/g_acc[1]) : 0.0f;
}

// ---------------- launch (k_bfs at idx 3 -> profiled) ----------------
extern "C" void kernel_launch(void* const* d_in, const int* in_sizes, int n_in,
                              void* d_out, int out_size) {
    const float* preds = (const float*)d_in[0];
    const float* low   = (const float*)d_in[1];
    const float* high  = (const float*)d_in[2];
    const float* roi   = (const float*)d_in[3];
    float* out = (float*)d_out;

    cudaFuncSetAttribute(k_boruvka, cudaFuncAttributeMaxDynamicSharedMemorySize, MST1_SMEM);
    cudaFuncSetAttribute(k_bfs,     cudaFuncAttributeMaxDynamicSharedMemorySize, BFS_SMEM);
    cudaFuncSetAttribute(k_filter,  cudaFuncAttributeMaxDynamicSharedMemorySize, FILT_SMEM);

    k_edgew_hi_part<<<dim3((Ee + 127)/128, 8, Bq), 128>>>(high);   // idx0
    k_edgew_reduce_low<<<dim3((Ee + 255)/256, Bq), 256>>>(low);    // idx1
    k_boruvka<<<8, 1024, MST1_SMEM>>>();                           // idx2
    k_bfs<<<8, 1024, BFS_SMEM>>>();                                // idx3 <- profiled
    k_prep<<<(Bq*CCn*Nn + 255)/256, 256>>>(preds);                 // idx4
    k_filter<<<Bq*22, FNT, FILT_SMEM>>>(1);                        // idx5
    k_filter<<<Bq*22, FNT, FILT_SMEM>>>(2);                        // idx6
    k_loss<<<512, 256>>>(roi);                                     // idx7
    k_final<<<1, 1>>>(out);                                        // idx8
}

// round 13
// speedup vs baseline: 2.2749x; 1.2195x over previous
#include <cuda_runtime.h>
#include <math.h>

// Problem constants
#define Bq 4
#define CCn 21
#define Hh 96
#define Ww 96
#define Nn (Hh*Ww)          // 9216
#define EH (Hh*(Ww-1))      // 9120
#define EV ((Hh-1)*Ww)      // 9120
#define Ee (EH+EV)          // 18240
#define CL 3
#define CHh 512
#define ROOT (48*Ww + 48)   // center root: tree filter is root-invariant; halves BFS depth

// ---- device scratch (static, no allocation) ----
__device__ float g_prob[Bq*CCn*Nn];
__device__ float g_part[Bq][8][Ee];
__device__ float g_wE[2][Bq][Ee];
__device__ unsigned char g_flag[2][Bq][Ee];  // MST edge markers (boruvka -> bfs handoff)
__device__ int   g_order[2][Bq][Nn];         // node id at BFS position k
__device__ int   g_pp[2][Bq][Nn];            // BFS position of parent, per position k
__device__ float g_Wp[2][Bq][Nn];            // edge weight exp(-d2/sigma), per position k
__device__ int   g_levelStart[2][Bq][Nn+2];
__device__ int   g_nLevels[2][Bq];
__device__ float g_F1[Bq*22*Nn];
__device__ float g_F2[Bq*22*Nn];
__device__ double g_acc[2];

__device__ __forceinline__ void edge_ep(int e, int& a, int& b) {
    if (e < EH) { int r = e / (Ww-1); int c = e - r*(Ww-1); a = r*Ww + c; b = a + 1; }
    else        { int e2 = e - EH;    a = e2;               b = e2 + Ww; }
}

// ---------------- K1: sigmoid + zero accumulators ----------------
__global__ void k_prep(const float* __restrict__ preds) {
    int i = blockIdx.x*blockDim.x + threadIdx.x;
    if (blockIdx.x == 0 && threadIdx.x == 0) { g_acc[0] = 0.0; g_acc[1] = 0.0; }
    if (i < Bq*CCn*Nn) g_prob[i] = 1.0f/(1.0f + expf(-preds[i]));
}

// ---------------- K2a: high-tree partials (fp32, 64-ch chunks, 4-way ILP) ----------------
__global__ void k_edgew_hi_part(const float* __restrict__ high) {
    int e = blockIdx.x*blockDim.x + threadIdx.x;
    if (e >= Ee) return;
    int chunk = blockIdx.y, b = blockIdx.z;
    int a, bn; edge_ep(e, a, bn);
    const float* f = high + ((size_t)b*CHh + (size_t)chunk*64)*Nn;
    float a0 = 0.f, a1 = 0.f, a2 = 0.f, a3 = 0.f;
    #pragma unroll
    for (int c = 0; c < 64; c += 4) {
        float d0 = __ldg(&f[(size_t)(c+0)*Nn + a]) - __ldg(&f[(size_t)(c+0)*Nn + bn]);
        float d1 = __ldg(&f[(size_t)(c+1)*Nn + a]) - __ldg(&f[(size_t)(c+1)*Nn + bn]);
        float d2 = __ldg(&f[(size_t)(c+2)*Nn + a]) - __ldg(&f[(size_t)(c+2)*Nn + bn]);
        float d3 = __ldg(&f[(size_t)(c+3)*Nn + a]) - __ldg(&f[(size_t)(c+3)*Nn + bn]);
        a0 = fmaf(d0, d0, a0);
        a1 = fmaf(d1, d1, a1);
        a2 = fmaf(d2, d2, a2);
        a3 = fmaf(d3, d3, a3);
    }
    g_part[b][chunk][e] = (a0 + a1) + (a2 + a3);
}

// ---------------- K2b: fp64 chunk combine (high) + low-tree weights, fused ----------------
__global__ void k_edgew_reduce_low(const float* __restrict__ low) {
    int e = blockIdx.x*blockDim.x + threadIdx.x;
    int b = blockIdx.y;
    if (e >= Ee) return;
    double s = 0.0;
    #pragma unroll
    for (int c = 0; c < 8; c++) s += (double)g_part[b][c][e];
    g_wE[1][b][e] = (float)s;
    int a, bn; edge_ep(e, a, bn);
    const float* f = low + (size_t)b*CL*Nn;
    double acc = 0.0;
    #pragma unroll
    for (int c = 0; c < CL; c++) {
        double d = (double)f[c*Nn + a] - (double)f[c*Nn + bn];
        acc += d*d;
    }
    g_wE[0][b][e] = (float)acc;
}

// ---------------- K3a: Boruvka MST (one block per (t,b)) ----------------
// smem: comp[0,36864) int[Nn] | best[36864,110592) u64[Nn] | active[110592,183552) int[Ee]
#define MST1_SMEM 183552

__global__ void __launch_bounds__(1024,1) k_boruvka() {
    extern __shared__ unsigned char smem[];
    const int t = blockIdx.x >> 2, b = blockIdx.x & 3;
    const int tid = threadIdx.x, NT = blockDim.x;

    int* comp = (int*)smem;
    unsigned long long* best = (unsigned long long*)(smem + 36864);
    int* active = (int*)(smem + 110592);
    unsigned char* flag = g_flag[t][b];

    __shared__ int s_merged, s_cnt[2];
    const float* wptr = g_wE[t][b];

    for (int e = tid; e < Ee; e += NT) { flag[e] = 0; active[e] = e; }
    for (int i = tid; i < Nn; i += NT) comp[i] = i;
    if (tid == 0) { s_cnt[0] = Ee; }
    __syncthreads();

    for (int round = 0; round < 16; round++) {
        const int p = round & 1;
        int cnt = s_cnt[p];
        if (cnt == 0) break;
        for (int i = tid; i < Nn; i += NT) best[i] = 0xFFFFFFFFFFFFFFFFULL;
        if (tid == 0) { s_merged = 0; s_cnt[p^1] = 0; }
        __syncthreads();                                   // B1

        int surv[18]; int nSurv = 0;
        for (int idx = tid; idx < cnt; idx += NT) {
            int e = active[idx];
            int a, bn; edge_ep(e, a, bn);
            int ca = comp[a], cb = comp[bn];
            if (ca != cb) {
                unsigned long long key =
                    ((unsigned long long)__float_as_uint(__ldg(&wptr[e])) << 32) | (unsigned)e;
                atomicMin(&best[ca], key);
                atomicMin(&best[cb], key);
                surv[nSurv++] = e;
            }
        }
        __syncthreads();                                   // B2

        int myRoot[10], myOther[10], myEdge[10]; int nMy = 0;
        for (int i = tid; i < Nn; i += NT) {
            if (comp[i] == i && best[i] != 0xFFFFFFFFFFFFFFFFULL) {
                unsigned long long k = best[i];
                int e = (int)(k & 0xFFFFFFFFu);
                int a, bn; edge_ep(e, a, bn);
                int ca = comp[a], cb = comp[bn];
                int other = (ca == i) ? cb : ca;
                bool mutual = (best[other] == k);
                if (!mutual || other < i) {
                    myRoot[nMy] = i; myOther[nMy] = other; myEdge[nMy] = e; nMy++;
                }
            }
        }
        if (nSurv) {
            int base = atomicAdd(&s_cnt[p^1], nSurv);
            for (int j = 0; j < nSurv; j++) active[base + j] = surv[j];
        }
        __syncthreads();                                   // B3
        for (int j = 0; j < nMy; j++) { comp[myRoot[j]] = myOther[j]; flag[myEdge[j]] = 1; }
        if (nMy) s_merged = 1;
        __syncthreads();                                   // B4
        if (!s_merged) break;
        // barrier-free full compression: chase to root (writes always point to ancestors)
        for (int i = tid; i < Nn; i += NT) {
            int r = comp[i];
            int rr = comp[r];
            while (rr != r) { r = rr; rr = comp[r]; }
            comp[i] = r;
        }
        __syncthreads();                                   // B5
    }
}

// ---------------- K3b: mask-based BFS, register-cursor + ballot alloc ----------------
// Tree on 4-connected grid: children(v) = direction-mask(v) minus incoming direction.
// Serial chain stores ONE word per child: node(14b) | indir(3b) | parentPos(14b).
// eid/pp/Wp decoded arithmetically in the parallel tail.
// dir bits: 0=E(+1) 1=W(-1) 2=S(+Ww) 3=N(-Ww); indir = d^1 (direction child->parent).
// smem: mask[0,36864) | packed[36864,73728)
#define BFS_SMEM 73728

__global__ void __launch_bounds__(1024,1) k_bfs() {
    extern __shared__ unsigned char smem[];
    const int t = blockIdx.x >> 2, b = blockIdx.x & 3;
    const int tid = threadIdx.x, NT = blockDim.x;

    int* mask   = (int*)smem;
    int* packed = (int*)(smem + 36864);
    const unsigned char* flag = g_flag[t][b];
    const float* wptr = g_wE[t][b];

    for (int i = tid; i < Nn; i += NT) mask[i] = 0;
    __syncthreads();
    for (int e = tid; e < Ee; e += NT) if (flag[e]) {
        int a, bn; edge_ep(e, a, bn);
        if (e < EH) { atomicOr(&mask[a], 1); atomicOr(&mask[bn], 2); }
        else        { atomicOr(&mask[a], 4); atomicOr(&mask[bn], 8); }
    }
    __syncthreads();
    if (tid == 0) {
        packed[0] = ROOT | (4 << 14);   // indir=4: clears no direction bits; pp bits = 0
        g_levelStart[t][b][0] = 0;
        g_levelStart[t][b][1] = 1;
    }
    __syncthreads();

    // ---- single-warp BFS: register head cursor, ballot-weighted prefix alloc ----
    if (tid < 32) {
        const unsigned FULL = 0xFFFFFFFFu;
        const int lane = tid;
        const unsigned ltm = (1u << lane) - 1u;
        int head = 1, lvl = 0, lo = 0, hi = 1;
        while (hi > lo) {
            for (int chunk = lo; chunk < hi; chunk += 32) {
                int k = chunk + lane;
                int v = 0, m = 0;
                if (k < hi) {
                    int pk = packed[k];
                    v = pk & 0x3FFF;
                    m = mask[v] & ~(1 << ((pk >> 14) & 7));
                }
                int nc = __popc(m);
                unsigned b0 = __ballot_sync(FULL, nc & 1);
                unsigned b1 = __ballot_sync(FULL, nc & 2);
                unsigned b2 = __ballot_sync(FULL, nc & 4);   // root can have 4 children
                int base = head + __popc(b0 & ltm) + 2*__popc(b1 & ltm) + 4*__popc(b2 & ltm);
                head += __popc(b0) + 2*__popc(b1) + 4*__popc(b2);
                if (m) {
                    int hib = k << 17;
                    #pragma unroll
                    for (int d = 0; d < 4; d++) {
                        if (m & (1 << d)) {
                            int c = v + ((d == 0) ? 1 : (d == 1) ? -1 : (d == 2) ? Ww : -Ww);
                            packed[base++] = c | ((d ^ 1) << 14) | hib;
                        }
                    }
                }
            }
            __syncwarp();
            lvl++;
            lo = hi; hi = head;
            if (lane == 0) g_levelStart[t][b][lvl + 1] = hi;
        }
        if (lane == 0) g_nLevels[t][b] = lvl;
    }
    __syncthreads();

    // ---- parallel tail: decode packed -> order/pp/Wp ----
    const float inv_sig = t ? 1.0f : 50.0f;   // sigma = 1.0 (high), 0.02 (low)
    for (int k = tid; k < Nn; k += NT) {
        int w = packed[k];
        int v = w & 0x3FFF;
        int indir = (w >> 14) & 7;
        g_order[t][b][k] = v;
        g_pp[t][b][k] = (w >> 17) & 0x3FFF;
        float Wv = 0.0f;
        if (k > 0) {
            int r = v / Ww, cc = v - r*Ww;
            int e;
            if (indir == 1)      e = r*(Ww-1) + cc - 1;   // parent is West
            else if (indir == 0) e = r*(Ww-1) + cc;        // parent is East
            else if (indir == 3) e = EH + v - Ww;          // parent is North
            else                 e = EH + v;               // parent is South
            Wv = expf(-__ldg(&wptr[e])*inv_sig);
        }
        g_Wp[t][b][k] = Wv;
    }
}

// ---------------- K5/K6: tree filter DP in BFS-order space ----------------
#define FILT_SMEM 184336
#define FNT 128

__global__ void __launch_bounds__(FNT,1) k_filter(int pass) {
    extern __shared__ unsigned char smem[];
    float* A  = (float*)smem;
    float* W  = A + Nn;
    int* PP   = (int*)(W + Nn);
    int* ORD  = PP + Nn;
    int* sLS  = ORD + Nn;

    const int t = pass - 1;
    const float* in = (pass == 1) ? g_prob : g_F1;
    const int cs = (pass == 1) ? CCn : 22;
    float* out = (pass == 1) ? g_F1 : g_F2;
    const bool normalize = (pass == 2);

    const int b = blockIdx.x / 22, ch = blockIdx.x % 22;
    const int tid = threadIdx.x;

    const int nLev = g_nLevels[t][b];
    const float* inb = in + (size_t)b*cs*Nn;
    const float* inn = in + ((size_t)b*cs + CCn)*Nn;

    for (int k = tid; k < Nn; k += FNT) {
        int v = g_order[t][b][k];
        ORD[k] = v;
        PP[k] = g_pp[t][b][k];
        W[k] = g_Wp[t][b][k];
        float val;
        if (ch < CCn) {
            val = inb[(size_t)ch*Nn + v];
            if (normalize) val /= inn[v];
        } else val = 1.0f;
        A[k] = val;
    }
    for (int l = tid; l < nLev + 2; l += FNT) sLS[l] = g_levelStart[t][b][l];
    __syncthreads();

    // up: leaf -> root
    for (int lev = nLev - 1; lev >= 1; lev--) {
        int lo = sLS[lev], hi = sLS[lev+1];
        if (hi - lo <= 32) {
            if (tid < 32) {
                int k = lo + tid;
                if (k < hi) atomicAdd(&A[PP[k]], W[k]*A[k]);
                __syncwarp();
            }
        } else {
            __syncthreads();
            for (int k = lo + tid; k < hi; k += FNT) atomicAdd(&A[PP[k]], W[k]*A[k]);
            __syncthreads();
        }
    }
    __syncthreads();
    // down: root -> leaf, in place
    for (int lev = 1; lev < nLev; lev++) {
        int lo = sLS[lev], hi = sLS[lev+1];
        if (hi - lo <= 32) {
            if (tid < 32) {
                int k = lo + tid;
                if (k < hi) {
                    float wk = W[k], ak = A[k];
                    A[k] = fmaf(wk, A[PP[k]] - wk*ak, ak);
                }
                __syncwarp();
            }
        } else {
            __syncthreads();
            for (int k = lo + tid; k < hi; k += FNT) {
                float wk = W[k], ak = A[k];
                A[k] = fmaf(wk, A[PP[k]] - wk*ak, ak);
            }
            __syncthreads();
        }
    }
    __syncthreads();
    float* outb = out + (size_t)(b*22 + ch)*Nn;
    for (int k = tid; k < Nn; k += FNT) outb[ORD[k]] = A[k];
}

// ---------------- K7: loss reduction ----------------
__global__ void k_loss(const float* __restrict__ roi) {
    __shared__ double red[256];
    long stride = (long)gridDim.x*blockDim.x;
    double ls = 0.0, ns = 0.0;
    for (long i = (long)blockIdx.x*blockDim.x + threadIdx.x; i < (long)Bq*CCn*Nn; i += stride) {
        int p = (int)(i % Nn);
        long bc = i / Nn;
        int c = (int)(bc % CCn);
        int b = (int)(bc / CCn);
        int row = p / Ww, col = p - row*Ww;
        float rv = roi[(size_t)b*(2*Hh)*(2*Ww) + (size_t)(2*row)*(2*Ww) + 2*col];
        float norm = g_F2[((size_t)b*22 + CCn)*Nn + p];
        float as = g_F2[((size_t)b*22 + c)*Nn + p] / norm;
        float pr = g_prob[i];
        ls += (double)(rv * fabsf(pr - as));
        if (c == 0) ns += (double)rv;
    }
    red[threadIdx.x] = ls; __syncthreads();
    for (int o = 128; o > 0; o >>= 1) { if (threadIdx.x < o) red[threadIdx.x] += red[threadIdx.x+o]; __syncthreads(); }
    if (threadIdx.x == 0) atomicAdd(&g_acc[0], red[0]);
    __syncthreads();
    red[threadIdx.x] = ns; __syncthreads();
    for (int o = 128; o > 0; o >>= 1) { if (threadIdx.x < o) red[threadIdx.x] += red[threadIdx.x+o]; __syncthreads(); }
    if (threadIdx.x == 0) atomicAdd(&g_acc[1], red[0]);
}

__global__ void k_final(float* out) {
    out[0] = (g_acc[1] > 0.0) ? (float)(g_acc[0]/g_acc[1]) : 0.0f;
}

// ---------------- launch (k_bfs at idx 3 -> profiled) ----------------
extern "C" void kernel_launch(void* const* d_in, const int* in_sizes, int n_in,
                              void* d_out, int out_size) {
    const float* preds = (const float*)d_in[0];
    const float* low   = (const float*)d_in[1];
    const float* high  = (const float*)d_in[2];
    const float* roi   = (const float*)d_in[3];
    float* out = (float*)d_out;

    cudaFuncSetAttribute(k_boruvka, cudaFuncAttributeMaxDynamicSharedMemorySize, MST1_SMEM);
    cudaFuncSetAttribute(k_bfs,     cudaFuncAttributeMaxDynamicSharedMemorySize, BFS_SMEM);
    cudaFuncSetAttribute(k_filter,  cudaFuncAttributeMaxDynamicSharedMemorySize, FILT_SMEM);

    k_edgew_hi_part<<<dim3((Ee + 127)/128, 8, Bq), 128>>>(high);   // idx0
    k_edgew_reduce_low<<<dim3((Ee + 255)/256, Bq), 256>>>(low);    // idx1
    k_boruvka<<<8, 1024, MST1_SMEM>>>();                           // idx2
    k_bfs<<<8, 1024, BFS_SMEM>>>();                                // idx3 <- profiled
    k_prep<<<(Bq*CCn*Nn + 255)/256, 256>>>(preds);                 // idx4
    k_filter<<<Bq*22, FNT, FILT_SMEM>>>(1);                        // idx5
    k_filter<<<Bq*22, FNT, FILT_SMEM>>>(2);                        // idx6
    k_loss<<<512, 256>>>(roi);                                     // idx7
    k_final<<<1, 1>>>(out);                                        // idx8
}